// round 5
// baseline (speedup 1.0000x reference)
#include <cuda_runtime.h>
#include <cuda_bf16.h>
#include <math.h>

// Problem constants
#define B   4
#define LQ  1024
#define LKV 2048
#define D   1024
#define H   16
#define HD  64
#define EPS 1e-5f
#define NEGV -1000000000.0f
#define ATTN_SCALE 0.125f   // 1/sqrt(64)

// ---------------------------------------------------------------------------
// Scratch (static device globals; allocation inside kernel_launch is banned)
// ---------------------------------------------------------------------------
__device__ float g_qn[(size_t)B * LQ * D];          // layernormed q
__device__ float g_kvn[(size_t)B * LKV * D];        // layernormed kv
__device__ float g_qh[(size_t)B * LQ * D];          // Q projection
__device__ float g_kv[(size_t)B * LKV * 2 * D];     // KV projection (k|v)
__device__ float g_attn[(size_t)B * LQ * D];        // attention output

// ---------------------------------------------------------------------------
// LayerNorm: one block per row of 1024, 256 threads, float4
// ---------------------------------------------------------------------------
__global__ __launch_bounds__(256) void ln_kernel(
    const float* __restrict__ x, const float* __restrict__ w,
    const float* __restrict__ b, float* __restrict__ y)
{
    const int row = blockIdx.x;
    const int tid = threadIdx.x;
    const float4* xr = (const float4*)(x + (size_t)row * D);
    float4 v = xr[tid];

    float s  = v.x + v.y + v.z + v.w;
    float s2 = v.x*v.x + v.y*v.y + v.z*v.z + v.w*v.w;

    // block reduce (s, s2)
    __shared__ float red[2][8];
    #pragma unroll
    for (int o = 16; o > 0; o >>= 1) {
        s  += __shfl_xor_sync(0xffffffffu, s,  o);
        s2 += __shfl_xor_sync(0xffffffffu, s2, o);
    }
    const int warp = tid >> 5, lane = tid & 31;
    if (lane == 0) { red[0][warp] = s; red[1][warp] = s2; }
    __syncthreads();
    if (warp == 0) {
        float a = (lane < 8) ? red[0][lane] : 0.f;
        float c = (lane < 8) ? red[1][lane] : 0.f;
        #pragma unroll
        for (int o = 4; o > 0; o >>= 1) {
            a += __shfl_xor_sync(0xffffffffu, a, o);
            c += __shfl_xor_sync(0xffffffffu, c, o);
        }
        if (lane == 0) { red[0][0] = a; red[1][0] = c; }
    }
    __syncthreads();
    const float mu  = red[0][0] * (1.0f / D);
    const float var = red[1][0] * (1.0f / D) - mu * mu;
    const float rstd = rsqrtf(var + EPS);

    const float4 wv = ((const float4*)w)[tid];
    const float4 bv = ((const float4*)b)[tid];
    float4 o;
    o.x = (v.x - mu) * rstd * wv.x + bv.x;
    o.y = (v.y - mu) * rstd * wv.y + bv.y;
    o.z = (v.z - mu) * rstd * wv.z + bv.z;
    o.w = (v.w - mu) * rstd * wv.w + bv.w;
    ((float4*)(y + (size_t)row * D))[tid] = o;
}

// ---------------------------------------------------------------------------
// SGEMM (NT): C[M,N] = A[M,K] @ W[N,K]^T + bias[N] (+ res[M,N])
// BM=BN=128, BK=8, 256 threads, 8x8 per thread.
// ---------------------------------------------------------------------------
#define BM 128
#define BN 128
#define BK 8
__global__ __launch_bounds__(256) void sgemm_nt(
    const float* __restrict__ A, const float* __restrict__ W,
    const float* __restrict__ bias, const float* __restrict__ res,
    float* __restrict__ C, int M, int N, int K)
{
    __shared__ float As[BK][BM];
    __shared__ float Ws[BK][BN];

    const int tid = threadIdx.x;
    const int tx = tid & 15;        // 0..15  (N dir)
    const int ty = tid >> 4;        // 0..15  (M dir)
    const int m0 = blockIdx.y * BM;
    const int n0 = blockIdx.x * BN;

    const int lr = tid >> 1;        // 0..127 row within tile
    const int lk = (tid & 1) * 4;   // 0 or 4

    const float* Ag = A + (size_t)(m0 + lr) * K + lk;
    const float* Wg = W + (size_t)(n0 + lr) * K + lk;

    float acc[8][8] = {};

    for (int k0 = 0; k0 < K; k0 += BK) {
        float4 a4 = *(const float4*)(Ag + k0);
        float4 w4 = *(const float4*)(Wg + k0);
        As[lk + 0][lr] = a4.x; As[lk + 1][lr] = a4.y;
        As[lk + 2][lr] = a4.z; As[lk + 3][lr] = a4.w;
        Ws[lk + 0][lr] = w4.x; Ws[lk + 1][lr] = w4.y;
        Ws[lk + 2][lr] = w4.z; Ws[lk + 3][lr] = w4.w;
        __syncthreads();

        #pragma unroll
        for (int k = 0; k < BK; k++) {
            float ra[8], rw[8];
            float4 t0 = *(const float4*)&As[k][ty * 8 + 0];
            float4 t1 = *(const float4*)&As[k][ty * 8 + 4];
            ra[0]=t0.x; ra[1]=t0.y; ra[2]=t0.z; ra[3]=t0.w;
            ra[4]=t1.x; ra[5]=t1.y; ra[6]=t1.z; ra[7]=t1.w;
            float4 u0 = *(const float4*)&Ws[k][tx * 8 + 0];
            float4 u1 = *(const float4*)&Ws[k][tx * 8 + 4];
            rw[0]=u0.x; rw[1]=u0.y; rw[2]=u0.z; rw[3]=u0.w;
            rw[4]=u1.x; rw[5]=u1.y; rw[6]=u1.z; rw[7]=u1.w;
            #pragma unroll
            for (int i = 0; i < 8; i++)
                #pragma unroll
                for (int j = 0; j < 8; j++)
                    acc[i][j] = fmaf(ra[i], rw[j], acc[i][j]);
        }
        __syncthreads();
    }

    #pragma unroll
    for (int i = 0; i < 8; i++) {
        const int m = m0 + ty * 8 + i;
        #pragma unroll
        for (int j = 0; j < 8; j++) {
            const int n = n0 + tx * 8 + j;
            float c = acc[i][j] + bias[n];
            if (res) c += res[(size_t)m * N + n];
            C[(size_t)m * N + n] = c;
        }
    }
}

// ---------------------------------------------------------------------------
// Flash attention, fp32, 64x64 tiles, online softmax, padding-mask skip.
// grid (LQ/64, H, B), 256 threads.
// mask is read as 32-bit words (int32 0/1 from bool conversion; a float32
// 1.0f encoding is also nonzero, so the !=0 test covers both).
// ---------------------------------------------------------------------------
__global__ __launch_bounds__(256) void flash_kernel(
    const float* __restrict__ Q, const float* __restrict__ KV,
    const int* __restrict__ mask, float* __restrict__ O)
{
    extern __shared__ float sm[];
    float* Qt  = sm;             // 4096
    float* Kt  = Qt + 4096;      // 4096
    float* Vs  = Kt + 4096;      // 4096
    float* St  = Vs + 4096;      // 4096
    float* rm  = St + 4096;      // 64
    float* rl  = rm + 64;        // 64
    float* rsc = rl + 64;        // 64

    const int tid = threadIdx.x;
    const int q0 = blockIdx.x * 64;
    const int h  = blockIdx.y;
    const int b  = blockIdx.z;
    const int tr = tid >> 4;     // 0..15
    const int tc = tid & 15;     // 0..15
    const int r0 = tr * 4;
    const int c0 = tc * 4;

    // load Q tile transposed: Qt[k][r]
    const float* Qg = Q + ((size_t)(b * LQ + q0)) * D + h * HD;
    #pragma unroll 4
    for (int i = tid; i < 64 * 16; i += 256) {
        const int r = i >> 4;
        const int kq = (i & 15) * 4;
        float4 v = *(const float4*)(Qg + (size_t)r * D + kq);
        Qt[(kq + 0) * 64 + r] = v.x;
        Qt[(kq + 1) * 64 + r] = v.y;
        Qt[(kq + 2) * 64 + r] = v.z;
        Qt[(kq + 3) * 64 + r] = v.w;
    }
    if (tid < 64) { rm[tid] = -3e38f; rl[tid] = 0.f; }
    float acc[4][4] = {};
    __syncthreads();

    const float* Kg = KV + (size_t)b * LKV * (2 * D) + h * HD;
    const float* Vg = Kg + D;
    const int* mg = mask + (size_t)b * LKV;

    for (int kv0 = 0; kv0 < LKV; kv0 += 64) {
        if (mg[kv0] != 0) break;   // padding mask is monotone: rest is masked

        // load K transposed (Kt[k][c]) and V direct (Vs[c][d])
        #pragma unroll 4
        for (int i = tid; i < 64 * 16; i += 256) {
            const int c = i >> 4;
            const int kq = (i & 15) * 4;
            const size_t rowoff = (size_t)(kv0 + c) * (2 * D);
            float4 kv4 = *(const float4*)(Kg + rowoff + kq);
            Kt[(kq + 0) * 64 + c] = kv4.x;
            Kt[(kq + 1) * 64 + c] = kv4.y;
            Kt[(kq + 2) * 64 + c] = kv4.z;
            Kt[(kq + 3) * 64 + c] = kv4.w;
            float4 v4 = *(const float4*)(Vg + rowoff + kq);
            *(float4*)(Vs + c * 64 + kq) = v4;
        }
        __syncthreads();

        // S = Q @ K^T (4x4 per thread)
        float s[4][4] = {};
        #pragma unroll
        for (int k = 0; k < 64; k++) {
            float4 qv = *(const float4*)(Qt + k * 64 + r0);
            float4 kv4 = *(const float4*)(Kt + k * 64 + c0);
            float rq[4] = {qv.x, qv.y, qv.z, qv.w};
            float rk[4] = {kv4.x, kv4.y, kv4.z, kv4.w};
            #pragma unroll
            for (int i = 0; i < 4; i++)
                #pragma unroll
                for (int j = 0; j < 4; j++)
                    s[i][j] = fmaf(rq[i], rk[j], s[i][j]);
        }
        // write S transposed (St[c][r]) with scale + mask
        #pragma unroll
        for (int j = 0; j < 4; j++) {
            const bool msk = (mg[kv0 + c0 + j] != 0);
            #pragma unroll
            for (int i = 0; i < 4; i++)
                St[(c0 + j) * 64 + r0 + i] = msk ? NEGV : s[i][j] * ATTN_SCALE;
        }
        __syncthreads();

        // per-row online softmax stats
        if (tid < 64) {
            const int r = tid;
            const float mold = rm[r];
            float mx = mold;
            #pragma unroll 8
            for (int c = 0; c < 64; c++) mx = fmaxf(mx, St[c * 64 + r]);
            float sum = 0.f;
            #pragma unroll 8
            for (int c = 0; c < 64; c++) {
                float p = __expf(St[c * 64 + r] - mx);
                sum += p;
                St[c * 64 + r] = p;
            }
            const float scale = __expf(mold - mx);
            rl[r] = rl[r] * scale + sum;
            rm[r] = mx;
            rsc[r] = scale;
        }
        __syncthreads();

        // rescale accumulators, then acc += P @ V
        float sci[4];
        #pragma unroll
        for (int i = 0; i < 4; i++) sci[i] = rsc[r0 + i];
        #pragma unroll
        for (int i = 0; i < 4; i++)
            #pragma unroll
            for (int j = 0; j < 4; j++)
                acc[i][j] *= sci[i];

        #pragma unroll
        for (int c = 0; c < 64; c++) {
            float4 pv = *(const float4*)(St + c * 64 + r0);
            float4 vv = *(const float4*)(Vs + c * 64 + c0);
            float rp[4] = {pv.x, pv.y, pv.z, pv.w};
            float rv[4] = {vv.x, vv.y, vv.z, vv.w};
            #pragma unroll
            for (int i = 0; i < 4; i++)
                #pragma unroll
                for (int j = 0; j < 4; j++)
                    acc[i][j] = fmaf(rp[i], rv[j], acc[i][j]);
        }
        __syncthreads();
    }

    // epilogue: normalize and write
    float invl[4];
    #pragma unroll
    for (int i = 0; i < 4; i++) invl[i] = 1.f / rl[r0 + i];
    float* Og = O + ((size_t)(b * LQ + q0)) * D + h * HD;
    #pragma unroll
    for (int i = 0; i < 4; i++)
        #pragma unroll
        for (int j = 0; j < 4; j++)
            Og[(size_t)(r0 + i) * D + c0 + j] = acc[i][j] * invl[i];
}

// ---------------------------------------------------------------------------
// Launch
// ---------------------------------------------------------------------------
extern "C" void kernel_launch(void* const* d_in, const int* in_sizes, int n_in,
                              void* d_out, int out_size)
{
    const float* q       = (const float*)d_in[0];
    const float* kv      = (const float*)d_in[1];
    const int*   mask    = (const int*)d_in[2];
    const float* nqw     = (const float*)d_in[3];
    const float* nqb     = (const float*)d_in[4];
    const float* nkw     = (const float*)d_in[5];
    const float* nkb     = (const float*)d_in[6];
    const float* Wq      = (const float*)d_in[7];
    const float* bq      = (const float*)d_in[8];
    const float* Wkv     = (const float*)d_in[9];
    const float* bkv     = (const float*)d_in[10];
    const float* Wo      = (const float*)d_in[11];
    const float* bo      = (const float*)d_in[12];
    float* out = (float*)d_out;

    float* qn   = nullptr; cudaGetSymbolAddress((void**)&qn,   g_qn);
    float* kvn  = nullptr; cudaGetSymbolAddress((void**)&kvn,  g_kvn);
    float* qh   = nullptr; cudaGetSymbolAddress((void**)&qh,   g_qh);
    float* kvp  = nullptr; cudaGetSymbolAddress((void**)&kvp,  g_kv);
    float* attn = nullptr; cudaGetSymbolAddress((void**)&attn, g_attn);

    // 1. LayerNorms
    ln_kernel<<<B * LQ, 256>>>(q, nqw, nqb, qn);
    ln_kernel<<<B * LKV, 256>>>(kv, nkw, nkb, kvn);

    // 2. Projections
    {
        dim3 grid(D / BN, (B * LQ) / BM);
        sgemm_nt<<<grid, 256>>>(qn, Wq, bq, nullptr, qh, B * LQ, D, D);
    }
    {
        dim3 grid((2 * D) / BN, (B * LKV) / BM);
        sgemm_nt<<<grid, 256>>>(kvn, Wkv, bkv, nullptr, kvp, B * LKV, 2 * D, D);
    }

    // 3. Flash attention
    {
        static int smem_set = 0;
        const int smem = (4 * 64 * 64 + 3 * 64) * (int)sizeof(float); // 66304 B
        if (!smem_set) {
            cudaFuncSetAttribute(flash_kernel,
                                 cudaFuncAttributeMaxDynamicSharedMemorySize, smem);
            smem_set = 1;
        }
        dim3 grid(LQ / 64, H, B);
        flash_kernel<<<grid, 256, smem>>>(qh, kvp, mask, attn);
    }

    // 4. Output projection + residual
    {
        dim3 grid(D / BN, (B * LQ) / BM);
        sgemm_nt<<<grid, 256>>>(attn, Wo, bo, q, out, B * LQ, D, D);
    }
}

// round 9
// speedup vs baseline: 1.8316x; 1.8316x over previous
#include <cuda_runtime.h>
#include <cuda_bf16.h>
#include <math.h>
#include <stdint.h>

// Problem constants
#define B   4
#define LQ  1024
#define LKV 2048
#define D   1024
#define H   16
#define HD  64
#define EPS 1e-5f
#define NEGV -1000000000.0f
#define ATTN_SCALE 0.125f   // 1/sqrt(64)

// tcgen05 is an arch-SPECIFIC (sm_103a) feature. The harness build also runs a
// plain sm_103 pass where those instructions are illegal, so every tcgen05 use
// is gated on the feature macro; the plain pass gets an FFMA fallback body.
#if defined(__CUDA_ARCH_FEAT_SM103_ALL)
#define HAS_TCGEN05 1
#else
#define HAS_TCGEN05 0
#endif

// ---------------------------------------------------------------------------
// Scratch (static device globals; allocation inside kernel_launch is banned)
// ---------------------------------------------------------------------------
__device__ float g_qn[(size_t)B * LQ * D];          // layernormed q
__device__ float g_kvn[(size_t)B * LKV * D];        // layernormed kv
__device__ float g_qh[(size_t)B * LQ * D];          // Q projection
__device__ float g_kv[(size_t)B * LKV * 2 * D];     // KV projection (k|v)
__device__ float g_attn[(size_t)B * LQ * D];        // attention output

// ---------------------------------------------------------------------------
// PTX helpers (guarded: only exist in the sm_103a compilation pass)
// ---------------------------------------------------------------------------
#if HAS_TCGEN05
__device__ __forceinline__ uint32_t smem_u32(const void* p) {
    uint32_t a;
    asm("{ .reg .u64 t; cvta.to.shared.u64 t, %1; cvt.u32.u64 %0, t; }"
        : "=r"(a) : "l"(p));
    return a;
}

__device__ __forceinline__ uint32_t elect_one_pred() {
    uint32_t pred;
    asm volatile(
        "{\n\t.reg .pred p;\n\t"
        "elect.sync _|p, 0xFFFFFFFF;\n\t"
        "selp.b32 %0, 1, 0, p;\n\t}"
        : "=r"(pred));
    return pred;
}

// SW128 K-major descriptor: LBO=1 (16B), SBO=64 (1024B = 8 rows x 128B), v1
static constexpr unsigned long long DESC_BASE =
    (2ull << 61) | (1ull << 46) | (64ull << 32) | (1ull << 16);
__device__ __forceinline__ uint64_t make_desc(uint32_t addr) {
    return DESC_BASE | ((uint64_t)(addr >> 4) & 0x3FFF);
}

__device__ __forceinline__ void mbar_init(uint32_t a, uint32_t cnt) {
    asm volatile("mbarrier.init.shared.b64 [%0], %1;" :: "r"(a), "r"(cnt) : "memory");
}
__device__ __forceinline__ void mbar_wait(uint32_t a, uint32_t parity) {
    asm volatile(
        "{\n\t.reg .pred P;\n"
        "LW_%=:\n\t"
        "mbarrier.try_wait.parity.acquire.cta.shared::cta.b64 P, [%0], %1, 0x989680;\n\t"
        "@P bra LD_%=;\n\t"
        "bra LW_%=;\n"
        "LD_%=:\n\t}"
        :: "r"(a), "r"(parity) : "memory");
}

__device__ __forceinline__ void tmem_alloc(uint32_t dst_smem, uint32_t ncols) {
    asm volatile("tcgen05.alloc.cta_group::1.sync.aligned.shared::cta.b32 [%0], %1;"
                 :: "r"(dst_smem), "r"(ncols) : "memory");
}
__device__ __forceinline__ void tmem_dealloc(uint32_t tmem, uint32_t ncols) {
    asm volatile("tcgen05.dealloc.cta_group::1.sync.aligned.b32 %0, %1;"
                 :: "r"(tmem), "r"(ncols));
}
__device__ __forceinline__ void tmem_relinquish() {
    asm volatile("tcgen05.relinquish_alloc_permit.cta_group::1.sync.aligned;");
}

// bf16 SS MMA (A desc, B desc), fp32 accumulate in TMEM
__device__ __forceinline__ void mma_bf16_ss(uint32_t d_tmem, uint64_t a_desc,
                                            uint64_t b_desc, uint32_t idesc,
                                            uint32_t acc) {
    asm volatile(
        "{\n\t.reg .pred p;\n\t"
        "setp.ne.u32 p, %4, 0;\n\t"
        "tcgen05.mma.cta_group::1.kind::f16 [%0], %1, %2, %3, {%5, %5, %5, %5}, p;\n\t}"
        :: "r"(d_tmem), "l"(a_desc), "l"(b_desc), "r"(idesc), "r"(acc), "r"(0u)
        : "memory");
}
__device__ __forceinline__ void mma_commit(uint32_t mbar) {
    asm volatile(
        "tcgen05.commit.cta_group::1.mbarrier::arrive::one.shared::cluster.b64 [%0];"
        :: "r"(mbar) : "memory");
}

#define TCGEN05_LD_X32(r, tmem_addr) \
    asm volatile( \
        "tcgen05.ld.sync.aligned.32x32b.x32.b32 " \
        "{%0, %1, %2, %3, %4, %5, %6, %7, " \
        " %8, %9, %10, %11, %12, %13, %14, %15, " \
        " %16, %17, %18, %19, %20, %21, %22, %23, " \
        " %24, %25, %26, %27, %28, %29, %30, %31}, [%32];" \
        : "=r"((r)[0]),  "=r"((r)[1]),  "=r"((r)[2]),  "=r"((r)[3]), \
          "=r"((r)[4]),  "=r"((r)[5]),  "=r"((r)[6]),  "=r"((r)[7]), \
          "=r"((r)[8]),  "=r"((r)[9]),  "=r"((r)[10]), "=r"((r)[11]), \
          "=r"((r)[12]), "=r"((r)[13]), "=r"((r)[14]), "=r"((r)[15]), \
          "=r"((r)[16]), "=r"((r)[17]), "=r"((r)[18]), "=r"((r)[19]), \
          "=r"((r)[20]), "=r"((r)[21]), "=r"((r)[22]), "=r"((r)[23]), \
          "=r"((r)[24]), "=r"((r)[25]), "=r"((r)[26]), "=r"((r)[27]), \
          "=r"((r)[28]), "=r"((r)[29]), "=r"((r)[30]), "=r"((r)[31]) \
        : "r"(tmem_addr))

__device__ __forceinline__ void tmem_wait_ld() {
    asm volatile("tcgen05.wait::ld.sync.aligned;" ::: "memory");
}
__device__ __forceinline__ void tc_fence_after() {
    asm volatile("tcgen05.fence::after_thread_sync;" ::: "memory");
}
__device__ __forceinline__ void tc_fence_before() {
    asm volatile("tcgen05.fence::before_thread_sync;" ::: "memory");
}
__device__ __forceinline__ void fence_async_smem() {
    asm volatile("fence.proxy.async.shared::cta;" ::: "memory");
}
#endif  // HAS_TCGEN05

#define SWZ(o) ((o) ^ (((o) >> 3) & 0x70))

// ---------------------------------------------------------------------------
// LayerNorm: one block per row of 1024, 256 threads, float4
// ---------------------------------------------------------------------------
__global__ __launch_bounds__(256) void ln_kernel(
    const float* __restrict__ x, const float* __restrict__ w,
    const float* __restrict__ b, float* __restrict__ y)
{
    const int row = blockIdx.x;
    const int tid = threadIdx.x;
    const float4* xr = (const float4*)(x + (size_t)row * D);
    float4 v = xr[tid];

    float s  = v.x + v.y + v.z + v.w;
    float s2 = v.x*v.x + v.y*v.y + v.z*v.z + v.w*v.w;

    __shared__ float red[2][8];
    #pragma unroll
    for (int o = 16; o > 0; o >>= 1) {
        s  += __shfl_xor_sync(0xffffffffu, s,  o);
        s2 += __shfl_xor_sync(0xffffffffu, s2, o);
    }
    const int warp = tid >> 5, lane = tid & 31;
    if (lane == 0) { red[0][warp] = s; red[1][warp] = s2; }
    __syncthreads();
    if (warp == 0) {
        float a = (lane < 8) ? red[0][lane] : 0.f;
        float c = (lane < 8) ? red[1][lane] : 0.f;
        #pragma unroll
        for (int o = 4; o > 0; o >>= 1) {
            a += __shfl_xor_sync(0xffffffffu, a, o);
            c += __shfl_xor_sync(0xffffffffu, c, o);
        }
        if (lane == 0) { red[0][0] = a; red[1][0] = c; }
    }
    __syncthreads();
    const float mu  = red[0][0] * (1.0f / D);
    const float var = red[1][0] * (1.0f / D) - mu * mu;
    const float rstd = rsqrtf(var + EPS);

    const float4 wv = ((const float4*)w)[tid];
    const float4 bv = ((const float4*)b)[tid];
    float4 o;
    o.x = (v.x - mu) * rstd * wv.x + bv.x;
    o.y = (v.y - mu) * rstd * wv.y + bv.y;
    o.z = (v.z - mu) * rstd * wv.z + bv.z;
    o.w = (v.w - mu) * rstd * wv.w + bv.w;
    ((float4*)(y + (size_t)row * D))[tid] = o;
}

// ---------------------------------------------------------------------------
// GEMM (NT): C[M,N] = A[M,K] @ W[N,K]^T + bias[N] (+ res)
// sm_103a image: tcgen05 bf16-split (hi/lo) SS MMA, fp32 TMEM accumulate.
// plain sm_103 image: FFMA 128x128x8 fallback (round-5 algorithm).
// Both bodies use the same launch shape: 256 threads, GEMM_SMEM dyn smem.
// ---------------------------------------------------------------------------
#define GK_CHUNK 64
#define TILE_BYTES (128 * 128)          // 128 rows x 64 bf16 x 2B = 16KB
#define STAGE_BYTES (4 * TILE_BYTES)    // Ahi, Alo, Whi, Wlo = 64KB
#define GEMM_SMEM (1024 + 2 * STAGE_BYTES)

// idesc: F32 acc, BF16 x BF16, N=128, M=128
#define GEMM_IDESC ((1u << 4) | (1u << 7) | (1u << 10) | ((128u / 8) << 17) | ((128u / 16) << 24))

#if HAS_TCGEN05
__device__ __forceinline__ void cvt_store8(const float* __restrict__ g,
                                           char* hi_p, char* lo_p) {
    float4 a0 = *(const float4*)g;
    float4 a1 = *(const float4*)(g + 4);
    __nv_bfloat162 h0 = __floats2bfloat162_rn(a0.x, a0.y);
    __nv_bfloat162 h1 = __floats2bfloat162_rn(a0.z, a0.w);
    __nv_bfloat162 h2 = __floats2bfloat162_rn(a1.x, a1.y);
    __nv_bfloat162 h3 = __floats2bfloat162_rn(a1.z, a1.w);
    float2 f0 = __bfloat1622float2(h0);
    float2 f1 = __bfloat1622float2(h1);
    float2 f2 = __bfloat1622float2(h2);
    float2 f3 = __bfloat1622float2(h3);
    __nv_bfloat162 l0 = __floats2bfloat162_rn(a0.x - f0.x, a0.y - f0.y);
    __nv_bfloat162 l1 = __floats2bfloat162_rn(a0.z - f1.x, a0.w - f1.y);
    __nv_bfloat162 l2 = __floats2bfloat162_rn(a1.x - f2.x, a1.y - f2.y);
    __nv_bfloat162 l3 = __floats2bfloat162_rn(a1.z - f3.x, a1.w - f3.y);
    uint4 uh, ul;
    uh.x = *reinterpret_cast<uint32_t*>(&h0);
    uh.y = *reinterpret_cast<uint32_t*>(&h1);
    uh.z = *reinterpret_cast<uint32_t*>(&h2);
    uh.w = *reinterpret_cast<uint32_t*>(&h3);
    ul.x = *reinterpret_cast<uint32_t*>(&l0);
    ul.y = *reinterpret_cast<uint32_t*>(&l1);
    ul.z = *reinterpret_cast<uint32_t*>(&l2);
    ul.w = *reinterpret_cast<uint32_t*>(&l3);
    *(uint4*)hi_p = uh;
    *(uint4*)lo_p = ul;
}
#endif

__global__ __launch_bounds__(256, 1)
void gemm_tc(const float* __restrict__ A, const float* __restrict__ W,
             const float* __restrict__ bias, const float* __restrict__ res,
             float* __restrict__ C, int M, int N, int K)
{
    extern __shared__ char smem[];
#if HAS_TCGEN05
    // ---- tcgen05 path ----
    // header: [0] tmem ptr, [8],[16] mbarriers. tiles at +1024 (1024-aligned).
    const int tid  = threadIdx.x;
    const int wid  = tid >> 5;
    const int lane = tid & 31;
    const int m0 = blockIdx.y * 128;
    const int n0 = blockIdx.x * 128;

    const uint32_t smem_base = smem_u32(smem);
    const uint32_t mbar[2] = { smem_base + 8, smem_base + 16 };

    if (wid == 0) tmem_alloc(smem_base, 128);
    if (tid == 0) { mbar_init(mbar[0], 1); mbar_init(mbar[1], 1); }
    __syncthreads();
    uint32_t tmem;
    asm volatile("ld.shared.b32 %0, [%1];" : "=r"(tmem) : "r"(smem_base));

    uint32_t ph[2] = {0, 0};
    const int nchunks = K / GK_CHUNK;   // 16 for K=1024

    for (int ch = 0; ch < nchunks; ch++) {
        const int buf = ch & 1;
        if (ch >= 2) {                  // reuse gate: MMAs of chunk ch-2 done?
            mbar_wait(mbar[buf], ph[buf]);
            ph[buf] ^= 1;
        }

        // load + split-convert this chunk: A[128 x 64], W[128 x 64]
        char* sb   = smem + 1024 + buf * STAGE_BYTES;
        char* sAh  = sb;
        char* sAl  = sb + TILE_BYTES;
        char* sWh  = sb + 2 * TILE_BYTES;
        char* sWl  = sb + 3 * TILE_BYTES;
        const int k0 = ch * GK_CHUNK;
        #pragma unroll
        for (int it = 0; it < 4; it++) {
            const int idx = tid + it * 256;        // 1024 items = 128 rows x 8 groups
            const int r = idx >> 3;
            const int g = idx & 7;
            const uint32_t off = SWZ(r * 128 + g * 16);
            cvt_store8(A + (size_t)(m0 + r) * K + k0 + g * 8, sAh + off, sAl + off);
            cvt_store8(W + (size_t)(n0 + r) * K + k0 + g * 8, sWh + off, sWl + off);
        }
        __syncthreads();

        if (wid == 0) {
            fence_async_smem();
            if (elect_one_pred()) {
                const uint32_t tb = smem_base + 1024 + buf * STAGE_BYTES;
                const uint64_t dAh = make_desc(tb);
                const uint64_t dAl = make_desc(tb + TILE_BYTES);
                const uint64_t dWh = make_desc(tb + 2 * TILE_BYTES);
                const uint64_t dWl = make_desc(tb + 3 * TILE_BYTES);
                #pragma unroll
                for (int ks = 0; ks < 4; ks++)      // hi * hi
                    mma_bf16_ss(tmem, dAh + ks * 2, dWh + ks * 2, GEMM_IDESC,
                                (ch != 0) || (ks != 0));
                #pragma unroll
                for (int ks = 0; ks < 4; ks++)      // hi * lo
                    mma_bf16_ss(tmem, dAh + ks * 2, dWl + ks * 2, GEMM_IDESC, 1);
                #pragma unroll
                for (int ks = 0; ks < 4; ks++)      // lo * hi
                    mma_bf16_ss(tmem, dAl + ks * 2, dWh + ks * 2, GEMM_IDESC, 1);
                mma_commit(mbar[buf]);
            }
        }
        // no sync needed: next iteration's mbar_wait gates smem reuse
    }

    // drain both buffers' outstanding commits
    mbar_wait(mbar[0], ph[0]);
    mbar_wait(mbar[1], ph[1]);
    tc_fence_after();

    // epilogue: warps 0-3 -> cols 0-63, warps 4-7 -> cols 64-127
    {
        const int sub   = wid & 3;
        const int cbase = (wid >> 2) * 64;
        uint32_t d[64];
        TCGEN05_LD_X32(d, tmem + cbase);
        TCGEN05_LD_X32(d + 32, tmem + cbase + 32);
        tmem_wait_ld();
        tc_fence_before();

        const int row = m0 + sub * 32 + lane;
        float* crow = C + (size_t)row * N + n0 + cbase;
        const float* rrow = res ? (res + (size_t)row * N + n0 + cbase) : nullptr;
        const float* brow = bias + n0 + cbase;
        #pragma unroll
        for (int j = 0; j < 64; j += 4) {
            float4 bb = *(const float4*)(brow + j);
            float4 o;
            o.x = __uint_as_float(d[j + 0]) + bb.x;
            o.y = __uint_as_float(d[j + 1]) + bb.y;
            o.z = __uint_as_float(d[j + 2]) + bb.z;
            o.w = __uint_as_float(d[j + 3]) + bb.w;
            if (rrow) {
                float4 rr = *(const float4*)(rrow + j);
                o.x += rr.x; o.y += rr.y; o.z += rr.z; o.w += rr.w;
            }
            *(float4*)(crow + j) = o;
        }
    }

    __syncthreads();
    if (wid == 0) {
        tmem_relinquish();
        tmem_dealloc(tmem, 128);
    }
#else
    // ---- FFMA fallback (plain sm_103 image): round-5 sgemm_nt algorithm ----
    float* As = (float*)smem;                    // [8][128]
    float* Ws = (float*)smem + 8 * 128;          // [8][128]

    const int tid = threadIdx.x;
    const int tx = tid & 15;
    const int ty = tid >> 4;
    const int m0 = blockIdx.y * 128;
    const int n0 = blockIdx.x * 128;

    const int lr = tid >> 1;
    const int lk = (tid & 1) * 4;

    const float* Ag = A + (size_t)(m0 + lr) * K + lk;
    const float* Wg = W + (size_t)(n0 + lr) * K + lk;

    float acc[8][8] = {};

    for (int k0 = 0; k0 < K; k0 += 8) {
        float4 a4 = *(const float4*)(Ag + k0);
        float4 w4 = *(const float4*)(Wg + k0);
        As[(lk + 0) * 128 + lr] = a4.x; As[(lk + 1) * 128 + lr] = a4.y;
        As[(lk + 2) * 128 + lr] = a4.z; As[(lk + 3) * 128 + lr] = a4.w;
        Ws[(lk + 0) * 128 + lr] = w4.x; Ws[(lk + 1) * 128 + lr] = w4.y;
        Ws[(lk + 2) * 128 + lr] = w4.z; Ws[(lk + 3) * 128 + lr] = w4.w;
        __syncthreads();

        #pragma unroll
        for (int k = 0; k < 8; k++) {
            float ra[8], rw[8];
            float4 t0 = *(const float4*)&As[k * 128 + ty * 8 + 0];
            float4 t1 = *(const float4*)&As[k * 128 + ty * 8 + 4];
            ra[0]=t0.x; ra[1]=t0.y; ra[2]=t0.z; ra[3]=t0.w;
            ra[4]=t1.x; ra[5]=t1.y; ra[6]=t1.z; ra[7]=t1.w;
            float4 u0 = *(const float4*)&Ws[k * 128 + tx * 8 + 0];
            float4 u1 = *(const float4*)&Ws[k * 128 + tx * 8 + 4];
            rw[0]=u0.x; rw[1]=u0.y; rw[2]=u0.z; rw[3]=u0.w;
            rw[4]=u1.x; rw[5]=u1.y; rw[6]=u1.z; rw[7]=u1.w;
            #pragma unroll
            for (int i = 0; i < 8; i++)
                #pragma unroll
                for (int j = 0; j < 8; j++)
                    acc[i][j] = fmaf(ra[i], rw[j], acc[i][j]);
        }
        __syncthreads();
    }

    #pragma unroll
    for (int i = 0; i < 8; i++) {
        const int m = m0 + ty * 8 + i;
        #pragma unroll
        for (int j = 0; j < 8; j++) {
            const int n = n0 + tx * 8 + j;
            float c = acc[i][j] + bias[n];
            if (res) c += res[(size_t)m * N + n];
            C[(size_t)m * N + n] = c;
        }
    }
#endif
}

// ---------------------------------------------------------------------------
// Flash attention, fp32, 64x64 tiles, online softmax, padding-mask skip.
// ---------------------------------------------------------------------------
__global__ __launch_bounds__(256) void flash_kernel(
    const float* __restrict__ Q, const float* __restrict__ KV,
    const int* __restrict__ mask, float* __restrict__ O)
{
    extern __shared__ float sm[];
    float* Qt  = sm;             // 4096
    float* Kt  = Qt + 4096;      // 4096
    float* Vs  = Kt + 4096;      // 4096
    float* St  = Vs + 4096;      // 4096
    float* rm  = St + 4096;      // 64
    float* rl  = rm + 64;        // 64
    float* rsc = rl + 64;        // 64

    const int tid = threadIdx.x;
    const int q0 = blockIdx.x * 64;
    const int h  = blockIdx.y;
    const int b  = blockIdx.z;
    const int tr = tid >> 4;
    const int tc = tid & 15;
    const int r0 = tr * 4;
    const int c0 = tc * 4;

    const float* Qg = Q + ((size_t)(b * LQ + q0)) * D + h * HD;
    #pragma unroll 4
    for (int i = tid; i < 64 * 16; i += 256) {
        const int r = i >> 4;
        const int kq = (i & 15) * 4;
        float4 v = *(const float4*)(Qg + (size_t)r * D + kq);
        Qt[(kq + 0) * 64 + r] = v.x;
        Qt[(kq + 1) * 64 + r] = v.y;
        Qt[(kq + 2) * 64 + r] = v.z;
        Qt[(kq + 3) * 64 + r] = v.w;
    }
    if (tid < 64) { rm[tid] = -3e38f; rl[tid] = 0.f; }
    float acc[4][4] = {};
    __syncthreads();

    const float* Kg = KV + (size_t)b * LKV * (2 * D) + h * HD;
    const float* Vg = Kg + D;
    const int* mg = mask + (size_t)b * LKV;

    for (int kv0 = 0; kv0 < LKV; kv0 += 64) {
        if (mg[kv0] != 0) break;   // padding mask is monotone

        #pragma unroll 4
        for (int i = tid; i < 64 * 16; i += 256) {
            const int c = i >> 4;
            const int kq = (i & 15) * 4;
            const size_t rowoff = (size_t)(kv0 + c) * (2 * D);
            float4 kv4 = *(const float4*)(Kg + rowoff + kq);
            Kt[(kq + 0) * 64 + c] = kv4.x;
            Kt[(kq + 1) * 64 + c] = kv4.y;
            Kt[(kq + 2) * 64 + c] = kv4.z;
            Kt[(kq + 3) * 64 + c] = kv4.w;
            float4 v4 = *(const float4*)(Vg + rowoff + kq);
            *(float4*)(Vs + c * 64 + kq) = v4;
        }
        __syncthreads();

        float s[4][4] = {};
        #pragma unroll
        for (int k = 0; k < 64; k++) {
            float4 qv = *(const float4*)(Qt + k * 64 + r0);
            float4 kv4 = *(const float4*)(Kt + k * 64 + c0);
            float rq[4] = {qv.x, qv.y, qv.z, qv.w};
            float rk[4] = {kv4.x, kv4.y, kv4.z, kv4.w};
            #pragma unroll
            for (int i = 0; i < 4; i++)
                #pragma unroll
                for (int j = 0; j < 4; j++)
                    s[i][j] = fmaf(rq[i], rk[j], s[i][j]);
        }
        #pragma unroll
        for (int j = 0; j < 4; j++) {
            const bool msk = (mg[kv0 + c0 + j] != 0);
            #pragma unroll
            for (int i = 0; i < 4; i++)
                St[(c0 + j) * 64 + r0 + i] = msk ? NEGV : s[i][j] * ATTN_SCALE;
        }
        __syncthreads();

        if (tid < 64) {
            const int r = tid;
            const float mold = rm[r];
            float mx = mold;
            #pragma unroll 8
            for (int c = 0; c < 64; c++) mx = fmaxf(mx, St[c * 64 + r]);
            float sum = 0.f;
            #pragma unroll 8
            for (int c = 0; c < 64; c++) {
                float p = __expf(St[c * 64 + r] - mx);
                sum += p;
                St[c * 64 + r] = p;
            }
            const float scale = __expf(mold - mx);
            rl[r] = rl[r] * scale + sum;
            rm[r] = mx;
            rsc[r] = scale;
        }
        __syncthreads();

        float sci[4];
        #pragma unroll
        for (int i = 0; i < 4; i++) sci[i] = rsc[r0 + i];
        #pragma unroll
        for (int i = 0; i < 4; i++)
            #pragma unroll
            for (int j = 0; j < 4; j++)
                acc[i][j] *= sci[i];

        #pragma unroll
        for (int c = 0; c < 64; c++) {
            float4 pv = *(const float4*)(St + c * 64 + r0);
            float4 vv = *(const float4*)(Vs + c * 64 + c0);
            float rp[4] = {pv.x, pv.y, pv.z, pv.w};
            float rv[4] = {vv.x, vv.y, vv.z, vv.w};
            #pragma unroll
            for (int i = 0; i < 4; i++)
                #pragma unroll
                for (int j = 0; j < 4; j++)
                    acc[i][j] = fmaf(rp[i], rv[j], acc[i][j]);
        }
        __syncthreads();
    }

    float invl[4];
    #pragma unroll
    for (int i = 0; i < 4; i++) invl[i] = 1.f / rl[r0 + i];
    float* Og = O + ((size_t)(b * LQ + q0)) * D + h * HD;
    #pragma unroll
    for (int i = 0; i < 4; i++)
        #pragma unroll
        for (int j = 0; j < 4; j++)
            Og[(size_t)(r0 + i) * D + c0 + j] = acc[i][j] * invl[i];
}

// ---------------------------------------------------------------------------
// Launch
// ---------------------------------------------------------------------------
extern "C" void kernel_launch(void* const* d_in, const int* in_sizes, int n_in,
                              void* d_out, int out_size)
{
    const float* q       = (const float*)d_in[0];
    const float* kv      = (const float*)d_in[1];
    const int*   mask    = (const int*)d_in[2];
    const float* nqw     = (const float*)d_in[3];
    const float* nqb     = (const float*)d_in[4];
    const float* nkw     = (const float*)d_in[5];
    const float* nkb     = (const float*)d_in[6];
    const float* Wq      = (const float*)d_in[7];
    const float* bq      = (const float*)d_in[8];
    const float* Wkv     = (const float*)d_in[9];
    const float* bkv     = (const float*)d_in[10];
    const float* Wo      = (const float*)d_in[11];
    const float* bo      = (const float*)d_in[12];
    float* out = (float*)d_out;

    float* qn   = nullptr; cudaGetSymbolAddress((void**)&qn,   g_qn);
    float* kvn  = nullptr; cudaGetSymbolAddress((void**)&kvn,  g_kvn);
    float* qh   = nullptr; cudaGetSymbolAddress((void**)&qh,   g_qh);
    float* kvp  = nullptr; cudaGetSymbolAddress((void**)&kvp,  g_kv);
    float* attn = nullptr; cudaGetSymbolAddress((void**)&attn, g_attn);

    static int attr_set = 0;
    if (!attr_set) {
        cudaFuncSetAttribute(gemm_tc,
                             cudaFuncAttributeMaxDynamicSharedMemorySize, GEMM_SMEM);
        const int fsmem = (4 * 64 * 64 + 3 * 64) * (int)sizeof(float);
        cudaFuncSetAttribute(flash_kernel,
                             cudaFuncAttributeMaxDynamicSharedMemorySize, fsmem);
        attr_set = 1;
    }

    // 1. LayerNorms
    ln_kernel<<<B * LQ, 256>>>(q, nqw, nqb, qn);
    ln_kernel<<<B * LKV, 256>>>(kv, nkw, nkb, kvn);

    // 2. Projections (tcgen05 bf16-split on sm_103a image)
    {
        dim3 grid(D / 128, (B * LQ) / 128);
        gemm_tc<<<grid, 256, GEMM_SMEM>>>(qn, Wq, bq, nullptr, qh, B * LQ, D, D);
    }
    {
        dim3 grid((2 * D) / 128, (B * LKV) / 128);
        gemm_tc<<<grid, 256, GEMM_SMEM>>>(kvn, Wkv, bkv, nullptr, kvp, B * LKV, 2 * D, D);
    }

    // 3. Flash attention
    {
        const int fsmem = (4 * 64 * 64 + 3 * 64) * (int)sizeof(float);
        dim3 grid(LQ / 64, H, B);
        flash_kernel<<<grid, 256, fsmem>>>(qh, kvp, mask, attn);
    }

    // 4. Output projection + residual
    {
        dim3 grid(D / 128, (B * LQ) / 128);
        gemm_tc<<<grid, 256, GEMM_SMEM>>>(attn, Wo, bo, q, out, B * LQ, D, D);
    }
}

// round 10
// speedup vs baseline: 3.9580x; 2.1610x over previous
#include <cuda_runtime.h>
#include <cuda_bf16.h>
#include <math.h>
#include <stdint.h>

// Problem constants
#define B   4
#define LQ  1024
#define LKV 2048
#define D   1024
#define H   16
#define HD  64
#define EPS 1e-5f
#define NEGV -1000000000.0f
#define ATTN_SCALE 0.125f   // 1/sqrt(64)

// tcgen05 is an arch-SPECIFIC (sm_103a) feature. The harness build also runs a
// plain sm_103 pass where those instructions are illegal, so every tcgen05 use
// is gated on the feature macro; the plain pass gets FFMA fallback bodies.
#if defined(__CUDA_ARCH_FEAT_SM103_ALL)
#define HAS_TCGEN05 1
#else
#define HAS_TCGEN05 0
#endif

// ---------------------------------------------------------------------------
// Scratch
// ---------------------------------------------------------------------------
__device__ float g_qn[(size_t)B * LQ * D];          // layernormed q
__device__ float g_kvn[(size_t)B * LKV * D];        // layernormed kv
__device__ float g_qh[(size_t)B * LQ * D];          // Q projection
__device__ float g_kv[(size_t)B * LKV * 2 * D];     // KV projection (k|v)
__device__ float g_attn[(size_t)B * LQ * D];        // attention output

// ---------------------------------------------------------------------------
// PTX helpers (sm_103a pass only)
// ---------------------------------------------------------------------------
#if HAS_TCGEN05
__device__ __forceinline__ uint32_t smem_u32(const void* p) {
    uint32_t a;
    asm("{ .reg .u64 t; cvta.to.shared.u64 t, %1; cvt.u32.u64 %0, t; }"
        : "=r"(a) : "l"(p));
    return a;
}

__device__ __forceinline__ uint32_t elect_one_pred() {
    uint32_t pred;
    asm volatile(
        "{\n\t.reg .pred p;\n\t"
        "elect.sync _|p, 0xFFFFFFFF;\n\t"
        "selp.b32 %0, 1, 0, p;\n\t}"
        : "=r"(pred));
    return pred;
}

// SW128 K-major descriptor: LBO=1 (16B), SBO=64 (1024B = 8 rows x 128B), v1
static constexpr unsigned long long DESC_BASE =
    (2ull << 61) | (1ull << 46) | (64ull << 32) | (1ull << 16);
__device__ __forceinline__ uint64_t make_desc(uint32_t addr) {
    return DESC_BASE | ((uint64_t)(addr >> 4) & 0x3FFF);
}

__device__ __forceinline__ void mbar_init(uint32_t a, uint32_t cnt) {
    asm volatile("mbarrier.init.shared.b64 [%0], %1;" :: "r"(a), "r"(cnt) : "memory");
}
__device__ __forceinline__ void mbar_wait(uint32_t a, uint32_t parity) {
    asm volatile(
        "{\n\t.reg .pred P;\n"
        "LW_%=:\n\t"
        "mbarrier.try_wait.parity.acquire.cta.shared::cta.b64 P, [%0], %1, 0x989680;\n\t"
        "@P bra LD_%=;\n\t"
        "bra LW_%=;\n"
        "LD_%=:\n\t}"
        :: "r"(a), "r"(parity) : "memory");
}

__device__ __forceinline__ void tmem_alloc(uint32_t dst_smem, uint32_t ncols) {
    asm volatile("tcgen05.alloc.cta_group::1.sync.aligned.shared::cta.b32 [%0], %1;"
                 :: "r"(dst_smem), "r"(ncols) : "memory");
}
__device__ __forceinline__ void tmem_dealloc(uint32_t tmem, uint32_t ncols) {
    asm volatile("tcgen05.dealloc.cta_group::1.sync.aligned.b32 %0, %1;"
                 :: "r"(tmem), "r"(ncols));
}
__device__ __forceinline__ void tmem_relinquish() {
    asm volatile("tcgen05.relinquish_alloc_permit.cta_group::1.sync.aligned;");
}

// bf16 SS MMA (A desc, B desc), fp32 accumulate in TMEM
__device__ __forceinline__ void mma_bf16_ss(uint32_t d_tmem, uint64_t a_desc,
                                            uint64_t b_desc, uint32_t idesc,
                                            uint32_t acc) {
    asm volatile(
        "{\n\t.reg .pred p;\n\t"
        "setp.ne.u32 p, %4, 0;\n\t"
        "tcgen05.mma.cta_group::1.kind::f16 [%0], %1, %2, %3, {%5, %5, %5, %5}, p;\n\t}"
        :: "r"(d_tmem), "l"(a_desc), "l"(b_desc), "r"(idesc), "r"(acc), "r"(0u)
        : "memory");
}
// bf16 TS MMA (A in TMEM, B desc)
__device__ __forceinline__ void mma_bf16_ts(uint32_t d_tmem, uint32_t a_tmem,
                                            uint64_t b_desc, uint32_t idesc,
                                            uint32_t acc) {
    asm volatile(
        "{\n\t.reg .pred p;\n\t"
        "setp.ne.u32 p, %4, 0;\n\t"
        "tcgen05.mma.cta_group::1.kind::f16 [%0], [%1], %2, %3, {%5, %5, %5, %5}, p;\n\t}"
        :: "r"(d_tmem), "r"(a_tmem), "l"(b_desc), "r"(idesc), "r"(acc), "r"(0u)
        : "memory");
}
__device__ __forceinline__ void mma_commit(uint32_t mbar) {
    asm volatile(
        "tcgen05.commit.cta_group::1.mbarrier::arrive::one.shared::cluster.b64 [%0];"
        :: "r"(mbar) : "memory");
}

#define TCGEN05_LD_X32(r, tmem_addr) \
    asm volatile( \
        "tcgen05.ld.sync.aligned.32x32b.x32.b32 " \
        "{%0, %1, %2, %3, %4, %5, %6, %7, " \
        " %8, %9, %10, %11, %12, %13, %14, %15, " \
        " %16, %17, %18, %19, %20, %21, %22, %23, " \
        " %24, %25, %26, %27, %28, %29, %30, %31}, [%32];" \
        : "=r"((r)[0]),  "=r"((r)[1]),  "=r"((r)[2]),  "=r"((r)[3]), \
          "=r"((r)[4]),  "=r"((r)[5]),  "=r"((r)[6]),  "=r"((r)[7]), \
          "=r"((r)[8]),  "=r"((r)[9]),  "=r"((r)[10]), "=r"((r)[11]), \
          "=r"((r)[12]), "=r"((r)[13]), "=r"((r)[14]), "=r"((r)[15]), \
          "=r"((r)[16]), "=r"((r)[17]), "=r"((r)[18]), "=r"((r)[19]), \
          "=r"((r)[20]), "=r"((r)[21]), "=r"((r)[22]), "=r"((r)[23]), \
          "=r"((r)[24]), "=r"((r)[25]), "=r"((r)[26]), "=r"((r)[27]), \
          "=r"((r)[28]), "=r"((r)[29]), "=r"((r)[30]), "=r"((r)[31]) \
        : "r"(tmem_addr))

#define TCGEN05_ST_X32(tmem_addr, r) \
    asm volatile( \
        "tcgen05.st.sync.aligned.32x32b.x32.b32 [%0], " \
        "{%1, %2, %3, %4, %5, %6, %7, %8, " \
        " %9, %10, %11, %12, %13, %14, %15, %16, " \
        " %17, %18, %19, %20, %21, %22, %23, %24, " \
        " %25, %26, %27, %28, %29, %30, %31, %32};" \
        :: "r"(tmem_addr), \
           "r"((r)[0]),  "r"((r)[1]),  "r"((r)[2]),  "r"((r)[3]), \
           "r"((r)[4]),  "r"((r)[5]),  "r"((r)[6]),  "r"((r)[7]), \
           "r"((r)[8]),  "r"((r)[9]),  "r"((r)[10]), "r"((r)[11]), \
           "r"((r)[12]), "r"((r)[13]), "r"((r)[14]), "r"((r)[15]), \
           "r"((r)[16]), "r"((r)[17]), "r"((r)[18]), "r"((r)[19]), \
           "r"((r)[20]), "r"((r)[21]), "r"((r)[22]), "r"((r)[23]), \
           "r"((r)[24]), "r"((r)[25]), "r"((r)[26]), "r"((r)[27]), \
           "r"((r)[28]), "r"((r)[29]), "r"((r)[30]), "r"((r)[31]) \
        : "memory")

__device__ __forceinline__ void tmem_wait_ld() {
    asm volatile("tcgen05.wait::ld.sync.aligned;" ::: "memory");
}
__device__ __forceinline__ void tmem_wait_st() {
    asm volatile("tcgen05.wait::st.sync.aligned;" ::: "memory");
}
__device__ __forceinline__ void tc_fence_after() {
    asm volatile("tcgen05.fence::after_thread_sync;" ::: "memory");
}
__device__ __forceinline__ void tc_fence_before() {
    asm volatile("tcgen05.fence::before_thread_sync;" ::: "memory");
}
__device__ __forceinline__ void fence_async_smem() {
    asm volatile("fence.proxy.async.shared::cta;" ::: "memory");
}
#endif  // HAS_TCGEN05

#define SWZ(o) ((o) ^ (((o) >> 3) & 0x70))

// ---------------------------------------------------------------------------
// LayerNorm: one block per row of 1024, 256 threads, float4
// ---------------------------------------------------------------------------
__global__ __launch_bounds__(256) void ln_kernel(
    const float* __restrict__ x, const float* __restrict__ w,
    const float* __restrict__ b, float* __restrict__ y)
{
    const int row = blockIdx.x;
    const int tid = threadIdx.x;
    const float4* xr = (const float4*)(x + (size_t)row * D);
    float4 v = xr[tid];

    float s  = v.x + v.y + v.z + v.w;
    float s2 = v.x*v.x + v.y*v.y + v.z*v.z + v.w*v.w;

    __shared__ float red[2][8];
    #pragma unroll
    for (int o = 16; o > 0; o >>= 1) {
        s  += __shfl_xor_sync(0xffffffffu, s,  o);
        s2 += __shfl_xor_sync(0xffffffffu, s2, o);
    }
    const int warp = tid >> 5, lane = tid & 31;
    if (lane == 0) { red[0][warp] = s; red[1][warp] = s2; }
    __syncthreads();
    if (warp == 0) {
        float a = (lane < 8) ? red[0][lane] : 0.f;
        float c = (lane < 8) ? red[1][lane] : 0.f;
        #pragma unroll
        for (int o = 4; o > 0; o >>= 1) {
            a += __shfl_xor_sync(0xffffffffu, a, o);
            c += __shfl_xor_sync(0xffffffffu, c, o);
        }
        if (lane == 0) { red[0][0] = a; red[1][0] = c; }
    }
    __syncthreads();
    const float mu  = red[0][0] * (1.0f / D);
    const float var = red[1][0] * (1.0f / D) - mu * mu;
    const float rstd = rsqrtf(var + EPS);

    const float4 wv = ((const float4*)w)[tid];
    const float4 bv = ((const float4*)b)[tid];
    float4 o;
    o.x = (v.x - mu) * rstd * wv.x + bv.x;
    o.y = (v.y - mu) * rstd * wv.y + bv.y;
    o.z = (v.z - mu) * rstd * wv.z + bv.z;
    o.w = (v.w - mu) * rstd * wv.w + bv.w;
    ((float4*)(y + (size_t)row * D))[tid] = o;
}

// ---------------------------------------------------------------------------
// GEMM (NT): C = A @ W^T + bias (+ res). tcgen05 bf16-split / FFMA fallback.
// ---------------------------------------------------------------------------
#define GK_CHUNK 64
#define TILE_BYTES (128 * 128)          // 16KB
#define STAGE_BYTES (4 * TILE_BYTES)    // 64KB
#define GEMM_SMEM (1024 + 2 * STAGE_BYTES)

// idesc: F32 acc, BF16 x BF16, N=128, M=128
#define GEMM_IDESC ((1u << 4) | (1u << 7) | (1u << 10) | ((128u / 8) << 17) | ((128u / 16) << 24))
// idesc: F32 acc, BF16 x BF16, N=64, M=128  (PV MMA)
#define PV_IDESC   ((1u << 4) | (1u << 7) | (1u << 10) | ((64u / 8) << 17) | ((128u / 16) << 24))

#if HAS_TCGEN05
__device__ __forceinline__ void cvt_store8(const float* __restrict__ g,
                                           char* hi_p, char* lo_p) {
    float4 a0 = *(const float4*)g;
    float4 a1 = *(const float4*)(g + 4);
    __nv_bfloat162 h0 = __floats2bfloat162_rn(a0.x, a0.y);
    __nv_bfloat162 h1 = __floats2bfloat162_rn(a0.z, a0.w);
    __nv_bfloat162 h2 = __floats2bfloat162_rn(a1.x, a1.y);
    __nv_bfloat162 h3 = __floats2bfloat162_rn(a1.z, a1.w);
    float2 f0 = __bfloat1622float2(h0);
    float2 f1 = __bfloat1622float2(h1);
    float2 f2 = __bfloat1622float2(h2);
    float2 f3 = __bfloat1622float2(h3);
    __nv_bfloat162 l0 = __floats2bfloat162_rn(a0.x - f0.x, a0.y - f0.y);
    __nv_bfloat162 l1 = __floats2bfloat162_rn(a0.z - f1.x, a0.w - f1.y);
    __nv_bfloat162 l2 = __floats2bfloat162_rn(a1.x - f2.x, a1.y - f2.y);
    __nv_bfloat162 l3 = __floats2bfloat162_rn(a1.z - f3.x, a1.w - f3.y);
    uint4 uh, ul;
    uh.x = *reinterpret_cast<uint32_t*>(&h0);
    uh.y = *reinterpret_cast<uint32_t*>(&h1);
    uh.z = *reinterpret_cast<uint32_t*>(&h2);
    uh.w = *reinterpret_cast<uint32_t*>(&h3);
    ul.x = *reinterpret_cast<uint32_t*>(&l0);
    ul.y = *reinterpret_cast<uint32_t*>(&l1);
    ul.z = *reinterpret_cast<uint32_t*>(&l2);
    ul.w = *reinterpret_cast<uint32_t*>(&l3);
    *(uint4*)hi_p = uh;
    *(uint4*)lo_p = ul;
}
#endif

__global__ __launch_bounds__(256, 1)
void gemm_tc(const float* __restrict__ A, const float* __restrict__ W,
             const float* __restrict__ bias, const float* __restrict__ res,
             float* __restrict__ C, int M, int N, int K)
{
    extern __shared__ char smem[];
#if HAS_TCGEN05
    const int tid  = threadIdx.x;
    const int wid  = tid >> 5;
    const int lane = tid & 31;
    const int m0 = blockIdx.y * 128;
    const int n0 = blockIdx.x * 128;

    const uint32_t smem_base = smem_u32(smem);
    const uint32_t mbar[2] = { smem_base + 8, smem_base + 16 };

    if (wid == 0) tmem_alloc(smem_base, 128);
    if (tid == 0) { mbar_init(mbar[0], 1); mbar_init(mbar[1], 1); }
    __syncthreads();
    uint32_t tmem;
    asm volatile("ld.shared.b32 %0, [%1];" : "=r"(tmem) : "r"(smem_base));

    uint32_t ph[2] = {0, 0};
    const int nchunks = K / GK_CHUNK;

    for (int ch = 0; ch < nchunks; ch++) {
        const int buf = ch & 1;
        if (ch >= 2) {
            mbar_wait(mbar[buf], ph[buf]);
            ph[buf] ^= 1;
        }

        char* sb   = smem + 1024 + buf * STAGE_BYTES;
        char* sAh  = sb;
        char* sAl  = sb + TILE_BYTES;
        char* sWh  = sb + 2 * TILE_BYTES;
        char* sWl  = sb + 3 * TILE_BYTES;
        const int k0 = ch * GK_CHUNK;
        #pragma unroll
        for (int it = 0; it < 4; it++) {
            const int idx = tid + it * 256;
            const int r = idx >> 3;
            const int g = idx & 7;
            const uint32_t off = SWZ(r * 128 + g * 16);
            cvt_store8(A + (size_t)(m0 + r) * K + k0 + g * 8, sAh + off, sAl + off);
            cvt_store8(W + (size_t)(n0 + r) * K + k0 + g * 8, sWh + off, sWl + off);
        }
        __syncthreads();

        if (wid == 0) {
            fence_async_smem();
            if (elect_one_pred()) {
                const uint32_t tb = smem_base + 1024 + buf * STAGE_BYTES;
                const uint64_t dAh = make_desc(tb);
                const uint64_t dAl = make_desc(tb + TILE_BYTES);
                const uint64_t dWh = make_desc(tb + 2 * TILE_BYTES);
                const uint64_t dWl = make_desc(tb + 3 * TILE_BYTES);
                #pragma unroll
                for (int ks = 0; ks < 4; ks++)
                    mma_bf16_ss(tmem, dAh + ks * 2, dWh + ks * 2, GEMM_IDESC,
                                (ch != 0) || (ks != 0));
                #pragma unroll
                for (int ks = 0; ks < 4; ks++)
                    mma_bf16_ss(tmem, dAh + ks * 2, dWl + ks * 2, GEMM_IDESC, 1);
                #pragma unroll
                for (int ks = 0; ks < 4; ks++)
                    mma_bf16_ss(tmem, dAl + ks * 2, dWh + ks * 2, GEMM_IDESC, 1);
                mma_commit(mbar[buf]);
            }
        }
    }

    mbar_wait(mbar[0], ph[0]);
    mbar_wait(mbar[1], ph[1]);
    tc_fence_after();

    {
        const int sub   = wid & 3;
        const int cbase = (wid >> 2) * 64;
        uint32_t d[64];
        TCGEN05_LD_X32(d, tmem + cbase);
        TCGEN05_LD_X32(d + 32, tmem + cbase + 32);
        tmem_wait_ld();
        tc_fence_before();

        const int row = m0 + sub * 32 + lane;
        float* crow = C + (size_t)row * N + n0 + cbase;
        const float* rrow = res ? (res + (size_t)row * N + n0 + cbase) : nullptr;
        const float* brow = bias + n0 + cbase;
        #pragma unroll
        for (int j = 0; j < 64; j += 4) {
            float4 bb = *(const float4*)(brow + j);
            float4 o;
            o.x = __uint_as_float(d[j + 0]) + bb.x;
            o.y = __uint_as_float(d[j + 1]) + bb.y;
            o.z = __uint_as_float(d[j + 2]) + bb.z;
            o.w = __uint_as_float(d[j + 3]) + bb.w;
            if (rrow) {
                float4 rr = *(const float4*)(rrow + j);
                o.x += rr.x; o.y += rr.y; o.z += rr.z; o.w += rr.w;
            }
            *(float4*)(crow + j) = o;
        }
    }

    __syncthreads();
    if (wid == 0) {
        tmem_relinquish();
        tmem_dealloc(tmem, 128);
    }
#else
    // FFMA fallback
    float* As = (float*)smem;
    float* Ws = (float*)smem + 8 * 128;

    const int tid = threadIdx.x;
    const int tx = tid & 15;
    const int ty = tid >> 4;
    const int m0 = blockIdx.y * 128;
    const int n0 = blockIdx.x * 128;

    const int lr = tid >> 1;
    const int lk = (tid & 1) * 4;

    const float* Ag = A + (size_t)(m0 + lr) * K + lk;
    const float* Wg = W + (size_t)(n0 + lr) * K + lk;

    float acc[8][8] = {};

    for (int k0 = 0; k0 < K; k0 += 8) {
        float4 a4 = *(const float4*)(Ag + k0);
        float4 w4 = *(const float4*)(Wg + k0);
        As[(lk + 0) * 128 + lr] = a4.x; As[(lk + 1) * 128 + lr] = a4.y;
        As[(lk + 2) * 128 + lr] = a4.z; As[(lk + 3) * 128 + lr] = a4.w;
        Ws[(lk + 0) * 128 + lr] = w4.x; Ws[(lk + 1) * 128 + lr] = w4.y;
        Ws[(lk + 2) * 128 + lr] = w4.z; Ws[(lk + 3) * 128 + lr] = w4.w;
        __syncthreads();

        #pragma unroll
        for (int k = 0; k < 8; k++) {
            float ra[8], rw[8];
            float4 t0 = *(const float4*)&As[k * 128 + ty * 8 + 0];
            float4 t1 = *(const float4*)&As[k * 128 + ty * 8 + 4];
            ra[0]=t0.x; ra[1]=t0.y; ra[2]=t0.z; ra[3]=t0.w;
            ra[4]=t1.x; ra[5]=t1.y; ra[6]=t1.z; ra[7]=t1.w;
            float4 u0 = *(const float4*)&Ws[k * 128 + tx * 8 + 0];
            float4 u1 = *(const float4*)&Ws[k * 128 + tx * 8 + 4];
            rw[0]=u0.x; rw[1]=u0.y; rw[2]=u0.z; rw[3]=u0.w;
            rw[4]=u1.x; rw[5]=u1.y; rw[6]=u1.z; rw[7]=u1.w;
            #pragma unroll
            for (int i = 0; i < 8; i++)
                #pragma unroll
                for (int j = 0; j < 8; j++)
                    acc[i][j] = fmaf(ra[i], rw[j], acc[i][j]);
        }
        __syncthreads();
    }

    #pragma unroll
    for (int i = 0; i < 8; i++) {
        const int m = m0 + ty * 8 + i;
        #pragma unroll
        for (int j = 0; j < 8; j++) {
            const int n = n0 + tx * 8 + j;
            float c = acc[i][j] + bias[n];
            if (res) c += res[(size_t)m * N + n];
            C[(size_t)m * N + n] = c;
        }
    }
#endif
}

// ---------------------------------------------------------------------------
// Flash attention.
// sm_103a image: tcgen05. Per CTA: 128 q rows x one (b,h). S via SS MMA
// (bf16-split Q,K), online softmax in regs, P split hi/lo STTM'd to TMEM,
// PV via TS MMA against V^T (bf16-split, blocked-atom smem). O in registers.
// Grid (LQ/128, H, B), 256 threads.
// plain image: FFMA fallback (two 64-row halves per CTA).
// ---------------------------------------------------------------------------
// TMEM columns
#define FL_S0   0      // S: 128 cols fp32
#define FL_O0   128    // PV: 64 cols fp32
#define FL_PHI  192    // P hi: 64 cols bf16x2 (K=128)
#define FL_PLO  256    // P lo: 64 cols
#define FL_TCOLS 512
// smem offsets (bytes)
#define FLQ_HI  1024
#define FLQ_LO  (1024 + 16384)
#define FLKV_HI (1024 + 32768)
#define FLKV_LO (1024 + 49152)
#define FLMASK  (1024 + 65536)       // 128 ints
#define FLBUF   (1024 + 66048)       // 2x 256 floats
#define FLASH_SMEM 131072            // pad -> 1 CTA/SM

__global__ __launch_bounds__(256, 1) void flash_kernel(
    const float* __restrict__ Q, const float* __restrict__ KV,
    const int* __restrict__ mask, float* __restrict__ O)
{
    extern __shared__ char smem[];
#if HAS_TCGEN05
    const int tid  = threadIdx.x;
    const int wid  = tid >> 5;
    const int lane = tid & 31;
    const int q0 = blockIdx.x * 128;
    const int h  = blockIdx.y;
    const int b  = blockIdx.z;
    const int half = wid >> 2;           // 0 or 1
    const int sub  = wid & 3;            // TMEM subpartition
    const int r    = sub * 32 + lane;    // q row within tile (0..127)
    const int cbase = half * 64;         // kv columns handled by this warp
    const int dbase = half * 32;         // d columns of O handled by this warp

    const uint32_t sb = smem_u32(smem);
    const uint32_t mbS = sb + 8, mbP = sb + 16;

    if (wid == 0) tmem_alloc(sb, FL_TCOLS);
    if (tid == 0) { mbar_init(mbS, 1); mbar_init(mbP, 1); }
    __syncthreads();
    uint32_t tmem;
    asm volatile("ld.shared.b32 %0, [%1];" : "=r"(tmem) : "r"(sb));

    // load Q tile (128 x 64) -> Qhi/Qlo (row = q, 64 bf16 = 128B rows, SW128)
    const float* Qg = Q + ((size_t)(b * LQ + q0)) * D + h * HD;
    #pragma unroll
    for (int it = 0; it < 4; it++) {
        const int idx = tid + it * 256;
        const int rq = idx >> 3;
        const int g  = idx & 7;
        const uint32_t off = SWZ(rq * 128 + g * 16);
        cvt_store8(Qg + (size_t)rq * D + g * 8,
                   smem + FLQ_HI + off, smem + FLQ_LO + off);
    }

    const float* Kg = KV + (size_t)b * LKV * (2 * D) + h * HD;
    const float* Vg = Kg + D;
    const int* mg = mask + (size_t)b * LKV;
    float* sbufA = (float*)(smem + FLBUF);
    float* sbufB = sbufA + 256;
    int* smask = (int*)(smem + FLMASK);

    float m_run = -3e38f, l_run = 0.f;
    float Oreg[32];
    #pragma unroll
    for (int j = 0; j < 32; j++) Oreg[j] = 0.f;

    uint32_t sph = 0, pph = 0;
    const uint64_t dQh = make_desc(sb + FLQ_HI);
    const uint64_t dQl = make_desc(sb + FLQ_LO);
    const uint64_t dKh = make_desc(sb + FLKV_HI);
    const uint64_t dKl = make_desc(sb + FLKV_LO);

    for (int kv0 = 0; kv0 < LKV; kv0 += 128) {
        if (mg[kv0] != 0) break;   // monotone padding mask

        // --- K tile (128 kv x 64 d) -> KVhi/KVlo ---
        #pragma unroll
        for (int it = 0; it < 4; it++) {
            const int idx = tid + it * 256;
            const int rk = idx >> 3;
            const int g  = idx & 7;
            const uint32_t off = SWZ(rk * 128 + g * 16);
            cvt_store8(Kg + (size_t)(kv0 + rk) * (2 * D) + g * 8,
                       smem + FLKV_HI + off, smem + FLKV_LO + off);
        }
        if (tid < 128) smask[tid] = mg[kv0 + tid];
        __syncthreads();

        // --- S = Q @ K^T  [128 x 128] ---
        if (wid == 0) {
            fence_async_smem();
            if (elect_one_pred()) {
                #pragma unroll
                for (int k = 0; k < 4; k++)
                    mma_bf16_ss(tmem + FL_S0, dQh + k * 2, dKh + k * 2, GEMM_IDESC, k != 0);
                #pragma unroll
                for (int k = 0; k < 4; k++)
                    mma_bf16_ss(tmem + FL_S0, dQh + k * 2, dKl + k * 2, GEMM_IDESC, 1);
                #pragma unroll
                for (int k = 0; k < 4; k++)
                    mma_bf16_ss(tmem + FL_S0, dQl + k * 2, dKh + k * 2, GEMM_IDESC, 1);
                mma_commit(mbS);
            }
        }
        mbar_wait(mbS, sph); sph ^= 1;

        // --- V^T tile: [64 d rows x 128 kv cols], blocked SW128 atoms ---
        // (K smem consumed by the completed MMA; safe to overwrite)
        #pragma unroll
        for (int it = 0; it < 8; it++) {
            const int idx = tid + it * 256;      // (c:128, dgroup:16)
            const int c  = idx >> 4;
            const int d0 = (idx & 15) * 4;
            float4 v4 = *(const float4*)(Vg + (size_t)(kv0 + c) * (2 * D) + d0);
            #pragma unroll
            for (int j = 0; j < 4; j++) {
                const int row = d0 + j;
                const uint32_t off = (uint32_t)(((row >> 3) + (c >> 6) * 8) * 1024
                                               + (row & 7) * 128 + (c & 63) * 2);
                const uint32_t so = SWZ(off);
                const float f = (j == 0) ? v4.x : (j == 1) ? v4.y : (j == 2) ? v4.z : v4.w;
                __nv_bfloat16 hb = __float2bfloat16(f);
                *(__nv_bfloat16*)(smem + FLKV_HI + so) = hb;
                *(__nv_bfloat16*)(smem + FLKV_LO + so) =
                    __float2bfloat16(f - __bfloat162float(hb));
            }
        }

        // --- read S, softmax ---
        tc_fence_after();
        float sv[64];
        TCGEN05_LD_X32((uint32_t*)sv,      tmem + FL_S0 + cbase);
        TCGEN05_LD_X32(((uint32_t*)sv) + 32, tmem + FL_S0 + cbase + 32);
        tmem_wait_ld();

        float mx = -3e38f;
        #pragma unroll
        for (int j = 0; j < 64; j++) {
            const float x = (smask[cbase + j] != 0) ? NEGV : sv[j] * ATTN_SCALE;
            sv[j] = x;
            mx = fmaxf(mx, x);
        }
        sbufA[half * 128 + r] = mx;
        __syncthreads();
        const float m_new = fmaxf(m_run, fmaxf(mx, sbufA[(1 - half) * 128 + r]));
        float sum = 0.f;
        #pragma unroll
        for (int j = 0; j < 64; j++) {
            const float p = __expf(sv[j] - m_new);
            sv[j] = p;
            sum += p;
        }
        sbufB[half * 128 + r] = sum;
        __syncthreads();
        sum += sbufB[(1 - half) * 128 + r];
        const float alpha = __expf(m_run - m_new);
        l_run = l_run * alpha + sum;
        m_run = m_new;

        // --- pack P hi/lo, store to TMEM ---
        {
            uint32_t phi[32], plo[32];
            #pragma unroll
            for (int j = 0; j < 32; j++) {
                const float p0 = sv[2 * j], p1 = sv[2 * j + 1];
                __nv_bfloat162 h2 = __floats2bfloat162_rn(p0, p1);
                float2 f2 = __bfloat1622float2(h2);
                __nv_bfloat162 l2 = __floats2bfloat162_rn(p0 - f2.x, p1 - f2.y);
                phi[j] = *reinterpret_cast<uint32_t*>(&h2);
                plo[j] = *reinterpret_cast<uint32_t*>(&l2);
            }
            const uint32_t wo = ((uint32_t)sub) << 21;
            TCGEN05_ST_X32(tmem + FL_PHI + half * 32 + wo, phi);
            TCGEN05_ST_X32(tmem + FL_PLO + half * 32 + wo, plo);
            tmem_wait_st();
        }
        tc_fence_before();
        __syncthreads();

        // --- PV: O_tile[128 x 64] = P[128 x 128] @ V[128 x 64] ---
        if (wid == 0) {
            fence_async_smem();
            if (elect_one_pred()) {
                tc_fence_after();
                const uint64_t dVh = make_desc(sb + FLKV_HI);
                const uint64_t dVl = make_desc(sb + FLKV_LO);
                #pragma unroll
                for (int k = 0; k < 8; k++) {
                    const uint64_t vo = (k < 4) ? (uint64_t)(k * 2)
                                               : (uint64_t)(512 + (k - 4) * 2);
                    mma_bf16_ts(tmem + FL_O0, tmem + FL_PHI + k * 8,
                                dVh + vo, PV_IDESC, k != 0);
                }
                #pragma unroll
                for (int k = 0; k < 8; k++) {
                    const uint64_t vo = (k < 4) ? (uint64_t)(k * 2)
                                               : (uint64_t)(512 + (k - 4) * 2);
                    mma_bf16_ts(tmem + FL_O0, tmem + FL_PHI + k * 8,
                                dVl + vo, PV_IDESC, 1);
                }
                #pragma unroll
                for (int k = 0; k < 8; k++) {
                    const uint64_t vo = (k < 4) ? (uint64_t)(k * 2)
                                               : (uint64_t)(512 + (k - 4) * 2);
                    mma_bf16_ts(tmem + FL_O0, tmem + FL_PLO + k * 8,
                                dVh + vo, PV_IDESC, 1);
                }
                mma_commit(mbP);
            }
        }
        mbar_wait(mbP, pph); pph ^= 1;
        tc_fence_after();
        {
            uint32_t pv[32];
            TCGEN05_LD_X32(pv, tmem + FL_O0 + dbase);
            tmem_wait_ld();
            #pragma unroll
            for (int j = 0; j < 32; j++)
                Oreg[j] = Oreg[j] * alpha + __uint_as_float(pv[j]);
        }
        __syncthreads();
    }

    // --- epilogue ---
    {
        const float inv = 1.f / l_run;
        float* Og = O + ((size_t)(b * LQ + q0 + r)) * D + h * HD + dbase;
        #pragma unroll
        for (int j = 0; j < 32; j += 4) {
            float4 o;
            o.x = Oreg[j + 0] * inv;
            o.y = Oreg[j + 1] * inv;
            o.z = Oreg[j + 2] * inv;
            o.w = Oreg[j + 3] * inv;
            *(float4*)(Og + j) = o;
        }
    }
    __syncthreads();
    if (wid == 0) {
        tmem_relinquish();
        tmem_dealloc(tmem, FL_TCOLS);
    }
#else
    // ---- FFMA fallback: two sequential 64-row q halves (round-5 algorithm) ----
    float* sm  = (float*)smem;
    float* Qt  = sm;
    float* Kt  = Qt + 4096;
    float* Vs  = Kt + 4096;
    float* St  = Vs + 4096;
    float* rm  = St + 4096;
    float* rl  = rm + 64;
    float* rsc = rl + 64;

    const int tid = threadIdx.x;
    const int h  = blockIdx.y;
    const int b  = blockIdx.z;
    const int tr = tid >> 4;
    const int tc = tid & 15;
    const int r0 = tr * 4;
    const int c0 = tc * 4;

    for (int qh = 0; qh < 2; qh++) {
        const int q0 = blockIdx.x * 128 + qh * 64;
        __syncthreads();

        const float* Qg = Q + ((size_t)(b * LQ + q0)) * D + h * HD;
        #pragma unroll 4
        for (int i = tid; i < 64 * 16; i += 256) {
            const int rr = i >> 4;
            const int kq = (i & 15) * 4;
            float4 v = *(const float4*)(Qg + (size_t)rr * D + kq);
            Qt[(kq + 0) * 64 + rr] = v.x;
            Qt[(kq + 1) * 64 + rr] = v.y;
            Qt[(kq + 2) * 64 + rr] = v.z;
            Qt[(kq + 3) * 64 + rr] = v.w;
        }
        if (tid < 64) { rm[tid] = -3e38f; rl[tid] = 0.f; }
        float acc[4][4] = {};
        __syncthreads();

        const float* Kg = KV + (size_t)b * LKV * (2 * D) + h * HD;
        const float* Vg = Kg + D;
        const int* mg = mask + (size_t)b * LKV;

        for (int kv0 = 0; kv0 < LKV; kv0 += 64) {
            if (mg[kv0] != 0) break;

            #pragma unroll 4
            for (int i = tid; i < 64 * 16; i += 256) {
                const int c = i >> 4;
                const int kq = (i & 15) * 4;
                const size_t rowoff = (size_t)(kv0 + c) * (2 * D);
                float4 kv4 = *(const float4*)(Kg + rowoff + kq);
                Kt[(kq + 0) * 64 + c] = kv4.x;
                Kt[(kq + 1) * 64 + c] = kv4.y;
                Kt[(kq + 2) * 64 + c] = kv4.z;
                Kt[(kq + 3) * 64 + c] = kv4.w;
                float4 v4 = *(const float4*)(Vg + rowoff + kq);
                *(float4*)(Vs + c * 64 + kq) = v4;
            }
            __syncthreads();

            float s[4][4] = {};
            #pragma unroll
            for (int k = 0; k < 64; k++) {
                float4 qv = *(const float4*)(Qt + k * 64 + r0);
                float4 kv4 = *(const float4*)(Kt + k * 64 + c0);
                float rq[4] = {qv.x, qv.y, qv.z, qv.w};
                float rk[4] = {kv4.x, kv4.y, kv4.z, kv4.w};
                #pragma unroll
                for (int i = 0; i < 4; i++)
                    #pragma unroll
                    for (int j = 0; j < 4; j++)
                        s[i][j] = fmaf(rq[i], rk[j], s[i][j]);
            }
            #pragma unroll
            for (int j = 0; j < 4; j++) {
                const bool msk = (mg[kv0 + c0 + j] != 0);
                #pragma unroll
                for (int i = 0; i < 4; i++)
                    St[(c0 + j) * 64 + r0 + i] = msk ? NEGV : s[i][j] * ATTN_SCALE;
            }
            __syncthreads();

            if (tid < 64) {
                const int rr = tid;
                const float mold = rm[rr];
                float mxx = mold;
                #pragma unroll 8
                for (int c = 0; c < 64; c++) mxx = fmaxf(mxx, St[c * 64 + rr]);
                float sum = 0.f;
                #pragma unroll 8
                for (int c = 0; c < 64; c++) {
                    float p = __expf(St[c * 64 + rr] - mxx);
                    sum += p;
                    St[c * 64 + rr] = p;
                }
                const float scale = __expf(mold - mxx);
                rl[rr] = rl[rr] * scale + sum;
                rm[rr] = mxx;
                rsc[rr] = scale;
            }
            __syncthreads();

            float sci[4];
            #pragma unroll
            for (int i = 0; i < 4; i++) sci[i] = rsc[r0 + i];
            #pragma unroll
            for (int i = 0; i < 4; i++)
                #pragma unroll
                for (int j = 0; j < 4; j++)
                    acc[i][j] *= sci[i];

            #pragma unroll
            for (int c = 0; c < 64; c++) {
                float4 pv = *(const float4*)(St + c * 64 + r0);
                float4 vv = *(const float4*)(Vs + c * 64 + c0);
                float rp[4] = {pv.x, pv.y, pv.z, pv.w};
                float rv[4] = {vv.x, vv.y, vv.z, vv.w};
                #pragma unroll
                for (int i = 0; i < 4; i++)
                    #pragma unroll
                    for (int j = 0; j < 4; j++)
                        acc[i][j] = fmaf(rp[i], rv[j], acc[i][j]);
            }
            __syncthreads();
        }

        float invl[4];
        #pragma unroll
        for (int i = 0; i < 4; i++) invl[i] = 1.f / rl[r0 + i];
        float* Og = O + ((size_t)(b * LQ + q0)) * D + h * HD;
        #pragma unroll
        for (int i = 0; i < 4; i++)
            #pragma unroll
            for (int j = 0; j < 4; j++)
                Og[(size_t)(r0 + i) * D + c0 + j] = acc[i][j] * invl[i];
    }
#endif
}

// ---------------------------------------------------------------------------
// Launch
// ---------------------------------------------------------------------------
extern "C" void kernel_launch(void* const* d_in, const int* in_sizes, int n_in,
                              void* d_out, int out_size)
{
    const float* q       = (const float*)d_in[0];
    const float* kv      = (const float*)d_in[1];
    const int*   mask    = (const int*)d_in[2];
    const float* nqw     = (const float*)d_in[3];
    const float* nqb     = (const float*)d_in[4];
    const float* nkw     = (const float*)d_in[5];
    const float* nkb     = (const float*)d_in[6];
    const float* Wq      = (const float*)d_in[7];
    const float* bq      = (const float*)d_in[8];
    const float* Wkv     = (const float*)d_in[9];
    const float* bkv     = (const float*)d_in[10];
    const float* Wo      = (const float*)d_in[11];
    const float* bo      = (const float*)d_in[12];
    float* out = (float*)d_out;

    float* qn   = nullptr; cudaGetSymbolAddress((void**)&qn,   g_qn);
    float* kvn  = nullptr; cudaGetSymbolAddress((void**)&kvn,  g_kvn);
    float* qh   = nullptr; cudaGetSymbolAddress((void**)&qh,   g_qh);
    float* kvp  = nullptr; cudaGetSymbolAddress((void**)&kvp,  g_kv);
    float* attn = nullptr; cudaGetSymbolAddress((void**)&attn, g_attn);

    static int attr_set = 0;
    if (!attr_set) {
        cudaFuncSetAttribute(gemm_tc,
                             cudaFuncAttributeMaxDynamicSharedMemorySize, GEMM_SMEM);
        cudaFuncSetAttribute(flash_kernel,
                             cudaFuncAttributeMaxDynamicSharedMemorySize, FLASH_SMEM);
        attr_set = 1;
    }

    // 1. LayerNorms
    ln_kernel<<<B * LQ, 256>>>(q, nqw, nqb, qn);
    ln_kernel<<<B * LKV, 256>>>(kv, nkw, nkb, kvn);

    // 2. Projections (tcgen05 bf16-split)
    {
        dim3 grid(D / 128, (B * LQ) / 128);
        gemm_tc<<<grid, 256, GEMM_SMEM>>>(qn, Wq, bq, nullptr, qh, B * LQ, D, D);
    }
    {
        dim3 grid((2 * D) / 128, (B * LKV) / 128);
        gemm_tc<<<grid, 256, GEMM_SMEM>>>(kvn, Wkv, bkv, nullptr, kvp, B * LKV, 2 * D, D);
    }

    // 3. Flash attention (tcgen05)
    {
        dim3 grid(LQ / 128, H, B);
        flash_kernel<<<grid, 256, FLASH_SMEM>>>(qh, kvp, mask, attn);
    }

    // 4. Output projection + residual
    {
        dim3 grid(D / 128, (B * LQ) / 128);
        gemm_tc<<<grid, 256, GEMM_SMEM>>>(attn, Wo, bo, q, out, B * LQ, D, D);
    }
}

// round 12
// speedup vs baseline: 4.4641x; 1.1279x over previous
#include <cuda_runtime.h>
#include <cuda_bf16.h>
#include <math.h>
#include <stdint.h>

// Problem constants
#define B   4
#define LQ  1024
#define LKV 2048
#define D   1024
#define H   16
#define HD  64
#define EPS 1e-5f
#define NEGV -1000000000.0f
#define ATTN_SCALE 0.125f   // 1/sqrt(64)

#if defined(__CUDA_ARCH_FEAT_SM103_ALL)
#define HAS_TCGEN05 1
#else
#define HAS_TCGEN05 0
#endif

// ---------------------------------------------------------------------------
// Scratch (bf16 hi/lo split is the interchange format between kernels)
// ---------------------------------------------------------------------------
__device__ __nv_bfloat16 g_qn_hi[(size_t)B * LQ * D];
__device__ __nv_bfloat16 g_qn_lo[(size_t)B * LQ * D];
__device__ __nv_bfloat16 g_kvn_hi[(size_t)B * LKV * D];
__device__ __nv_bfloat16 g_kvn_lo[(size_t)B * LKV * D];
__device__ __nv_bfloat16 g_wq_hi[(size_t)D * D];
__device__ __nv_bfloat16 g_wq_lo[(size_t)D * D];
__device__ __nv_bfloat16 g_wkv_hi[(size_t)2 * D * D];
__device__ __nv_bfloat16 g_wkv_lo[(size_t)2 * D * D];
__device__ __nv_bfloat16 g_wo_hi[(size_t)D * D];
__device__ __nv_bfloat16 g_wo_lo[(size_t)D * D];
__device__ __nv_bfloat16 g_qh_hi[(size_t)B * LQ * D];
__device__ __nv_bfloat16 g_qh_lo[(size_t)B * LQ * D];
__device__ __nv_bfloat16 g_kvp_hi[(size_t)B * LKV * 2 * D];
__device__ __nv_bfloat16 g_kvp_lo[(size_t)B * LKV * 2 * D];
__device__ __nv_bfloat16 g_attn_hi[(size_t)B * LQ * D];
__device__ __nv_bfloat16 g_attn_lo[(size_t)B * LQ * D];

// ---------------------------------------------------------------------------
// Common helpers (legal on both compile passes)
// ---------------------------------------------------------------------------
__device__ __forceinline__ uint32_t smem_u32(const void* p) {
    uint32_t a;
    asm("{ .reg .u64 t; cvta.to.shared.u64 t, %1; cvt.u32.u64 %0, t; }"
        : "=r"(a) : "l"(p));
    return a;
}

__device__ __forceinline__ void split2(float x, float y, uint32_t& h, uint32_t& l) {
    __nv_bfloat162 hb = __floats2bfloat162_rn(x, y);
    float2 f = __bfloat1622float2(hb);
    __nv_bfloat162 lb = __floats2bfloat162_rn(x - f.x, y - f.y);
    h = *reinterpret_cast<uint32_t*>(&hb);
    l = *reinterpret_cast<uint32_t*>(&lb);
}

__device__ __forceinline__ void cp_async16(uint32_t dst_smem, const void* src) {
    asm volatile("cp.async.cg.shared.global [%0], [%1], 16;"
                 :: "r"(dst_smem), "l"(__cvta_generic_to_global(src)) : "memory");
}
__device__ __forceinline__ void cp_commit() {
    asm volatile("cp.async.commit_group;" ::: "memory");
}
template<int N> __device__ __forceinline__ void cp_wait() {
    asm volatile("cp.async.wait_group %0;" :: "n"(N) : "memory");
}

#define SWZ(o) ((o) ^ (((o) >> 3) & 0x70))

// ---------------------------------------------------------------------------
// tcgen05 helpers (sm_103a pass only)
// ---------------------------------------------------------------------------
#if HAS_TCGEN05
__device__ __forceinline__ uint32_t elect_one_pred() {
    uint32_t pred;
    asm volatile(
        "{\n\t.reg .pred p;\n\t"
        "elect.sync _|p, 0xFFFFFFFF;\n\t"
        "selp.b32 %0, 1, 0, p;\n\t}"
        : "=r"(pred));
    return pred;
}

// SW128 K-major descriptor: LBO=1 (16B), SBO=64 (1024B), v1
static constexpr unsigned long long DESC_BASE =
    (2ull << 61) | (1ull << 46) | (64ull << 32) | (1ull << 16);
__device__ __forceinline__ uint64_t make_desc(uint32_t addr) {
    return DESC_BASE | ((uint64_t)(addr >> 4) & 0x3FFF);
}

__device__ __forceinline__ void mbar_init(uint32_t a, uint32_t cnt) {
    asm volatile("mbarrier.init.shared.b64 [%0], %1;" :: "r"(a), "r"(cnt) : "memory");
}
__device__ __forceinline__ void mbar_wait(uint32_t a, uint32_t parity) {
    asm volatile(
        "{\n\t.reg .pred P;\n"
        "LW_%=:\n\t"
        "mbarrier.try_wait.parity.acquire.cta.shared::cta.b64 P, [%0], %1, 0x989680;\n\t"
        "@P bra LD_%=;\n\t"
        "bra LW_%=;\n"
        "LD_%=:\n\t}"
        :: "r"(a), "r"(parity) : "memory");
}

__device__ __forceinline__ void tmem_alloc(uint32_t dst_smem, uint32_t ncols) {
    asm volatile("tcgen05.alloc.cta_group::1.sync.aligned.shared::cta.b32 [%0], %1;"
                 :: "r"(dst_smem), "r"(ncols) : "memory");
}
__device__ __forceinline__ void tmem_dealloc(uint32_t tmem, uint32_t ncols) {
    asm volatile("tcgen05.dealloc.cta_group::1.sync.aligned.b32 %0, %1;"
                 :: "r"(tmem), "r"(ncols));
}
__device__ __forceinline__ void tmem_relinquish() {
    asm volatile("tcgen05.relinquish_alloc_permit.cta_group::1.sync.aligned;");
}

__device__ __forceinline__ void mma_bf16_ss(uint32_t d_tmem, uint64_t a_desc,
                                            uint64_t b_desc, uint32_t idesc,
                                            uint32_t acc) {
    asm volatile(
        "{\n\t.reg .pred p;\n\t"
        "setp.ne.u32 p, %4, 0;\n\t"
        "tcgen05.mma.cta_group::1.kind::f16 [%0], %1, %2, %3, {%5, %5, %5, %5}, p;\n\t}"
        :: "r"(d_tmem), "l"(a_desc), "l"(b_desc), "r"(idesc), "r"(acc), "r"(0u)
        : "memory");
}
__device__ __forceinline__ void mma_bf16_ts(uint32_t d_tmem, uint32_t a_tmem,
                                            uint64_t b_desc, uint32_t idesc,
                                            uint32_t acc) {
    asm volatile(
        "{\n\t.reg .pred p;\n\t"
        "setp.ne.u32 p, %4, 0;\n\t"
        "tcgen05.mma.cta_group::1.kind::f16 [%0], [%1], %2, %3, {%5, %5, %5, %5}, p;\n\t}"
        :: "r"(d_tmem), "r"(a_tmem), "l"(b_desc), "r"(idesc), "r"(acc), "r"(0u)
        : "memory");
}
__device__ __forceinline__ void mma_commit(uint32_t mbar) {
    asm volatile(
        "tcgen05.commit.cta_group::1.mbarrier::arrive::one.shared::cluster.b64 [%0];"
        :: "r"(mbar) : "memory");
}

#define TCGEN05_LD_X32(r, tmem_addr) \
    asm volatile( \
        "tcgen05.ld.sync.aligned.32x32b.x32.b32 " \
        "{%0, %1, %2, %3, %4, %5, %6, %7, " \
        " %8, %9, %10, %11, %12, %13, %14, %15, " \
        " %16, %17, %18, %19, %20, %21, %22, %23, " \
        " %24, %25, %26, %27, %28, %29, %30, %31}, [%32];" \
        : "=r"((r)[0]),  "=r"((r)[1]),  "=r"((r)[2]),  "=r"((r)[3]), \
          "=r"((r)[4]),  "=r"((r)[5]),  "=r"((r)[6]),  "=r"((r)[7]), \
          "=r"((r)[8]),  "=r"((r)[9]),  "=r"((r)[10]), "=r"((r)[11]), \
          "=r"((r)[12]), "=r"((r)[13]), "=r"((r)[14]), "=r"((r)[15]), \
          "=r"((r)[16]), "=r"((r)[17]), "=r"((r)[18]), "=r"((r)[19]), \
          "=r"((r)[20]), "=r"((r)[21]), "=r"((r)[22]), "=r"((r)[23]), \
          "=r"((r)[24]), "=r"((r)[25]), "=r"((r)[26]), "=r"((r)[27]), \
          "=r"((r)[28]), "=r"((r)[29]), "=r"((r)[30]), "=r"((r)[31]) \
        : "r"(tmem_addr))

#define TCGEN05_ST_X32(tmem_addr, r) \
    asm volatile( \
        "tcgen05.st.sync.aligned.32x32b.x32.b32 [%0], " \
        "{%1, %2, %3, %4, %5, %6, %7, %8, " \
        " %9, %10, %11, %12, %13, %14, %15, %16, " \
        " %17, %18, %19, %20, %21, %22, %23, %24, " \
        " %25, %26, %27, %28, %29, %30, %31, %32};" \
        :: "r"(tmem_addr), \
           "r"((r)[0]),  "r"((r)[1]),  "r"((r)[2]),  "r"((r)[3]), \
           "r"((r)[4]),  "r"((r)[5]),  "r"((r)[6]),  "r"((r)[7]), \
           "r"((r)[8]),  "r"((r)[9]),  "r"((r)[10]), "r"((r)[11]), \
           "r"((r)[12]), "r"((r)[13]), "r"((r)[14]), "r"((r)[15]), \
           "r"((r)[16]), "r"((r)[17]), "r"((r)[18]), "r"((r)[19]), \
           "r"((r)[20]), "r"((r)[21]), "r"((r)[22]), "r"((r)[23]), \
           "r"((r)[24]), "r"((r)[25]), "r"((r)[26]), "r"((r)[27]), \
           "r"((r)[28]), "r"((r)[29]), "r"((r)[30]), "r"((r)[31]) \
        : "memory")

__device__ __forceinline__ void tmem_wait_ld() {
    asm volatile("tcgen05.wait::ld.sync.aligned;" ::: "memory");
}
__device__ __forceinline__ void tmem_wait_st() {
    asm volatile("tcgen05.wait::st.sync.aligned;" ::: "memory");
}
__device__ __forceinline__ void tc_fence_after() {
    asm volatile("tcgen05.fence::after_thread_sync;" ::: "memory");
}
__device__ __forceinline__ void tc_fence_before() {
    asm volatile("tcgen05.fence::before_thread_sync;" ::: "memory");
}
__device__ __forceinline__ void fence_async_smem() {
    asm volatile("fence.proxy.async.shared::cta;" ::: "memory");
}
#endif  // HAS_TCGEN05

// ---------------------------------------------------------------------------
// LayerNorm -> split bf16 (hi, lo)
// ---------------------------------------------------------------------------
__global__ __launch_bounds__(256) void ln_split_kernel(
    const float* __restrict__ x, const float* __restrict__ w,
    const float* __restrict__ b,
    __nv_bfloat16* __restrict__ yh, __nv_bfloat16* __restrict__ yl)
{
    const int row = blockIdx.x;
    const int tid = threadIdx.x;
    const float4* xr = (const float4*)(x + (size_t)row * D);
    float4 v = xr[tid];

    float s  = v.x + v.y + v.z + v.w;
    float s2 = v.x*v.x + v.y*v.y + v.z*v.z + v.w*v.w;

    __shared__ float red[2][8];
    #pragma unroll
    for (int o = 16; o > 0; o >>= 1) {
        s  += __shfl_xor_sync(0xffffffffu, s,  o);
        s2 += __shfl_xor_sync(0xffffffffu, s2, o);
    }
    const int warp = tid >> 5, lane = tid & 31;
    if (lane == 0) { red[0][warp] = s; red[1][warp] = s2; }
    __syncthreads();
    if (warp == 0) {
        float a = (lane < 8) ? red[0][lane] : 0.f;
        float c = (lane < 8) ? red[1][lane] : 0.f;
        #pragma unroll
        for (int o = 4; o > 0; o >>= 1) {
            a += __shfl_xor_sync(0xffffffffu, a, o);
            c += __shfl_xor_sync(0xffffffffu, c, o);
        }
        if (lane == 0) { red[0][0] = a; red[1][0] = c; }
    }
    __syncthreads();
    const float mu  = red[0][0] * (1.0f / D);
    const float var = red[1][0] * (1.0f / D) - mu * mu;
    const float rstd = rsqrtf(var + EPS);

    const float4 wv = ((const float4*)w)[tid];
    const float4 bv = ((const float4*)b)[tid];
    float4 o;
    o.x = (v.x - mu) * rstd * wv.x + bv.x;
    o.y = (v.y - mu) * rstd * wv.y + bv.y;
    o.z = (v.z - mu) * rstd * wv.z + bv.z;
    o.w = (v.w - mu) * rstd * wv.w + bv.w;

    uint32_t h0, l0, h1, l1;
    split2(o.x, o.y, h0, l0);
    split2(o.z, o.w, h1, l1);
    ((uint2*)(yh + (size_t)row * D))[tid] = make_uint2(h0, h1);
    ((uint2*)(yl + (size_t)row * D))[tid] = make_uint2(l0, l1);
}

// Generic fp32 -> (hi, lo) bf16 split (weights)
__global__ __launch_bounds__(256) void split_kernel(
    const float4* __restrict__ src, uint2* __restrict__ hi,
    uint2* __restrict__ lo, int n4)
{
    const int i = blockIdx.x * blockDim.x + threadIdx.x;
    if (i < n4) {
        float4 v = src[i];
        uint32_t h0, l0, h1, l1;
        split2(v.x, v.y, h0, l0);
        split2(v.z, v.w, h1, l1);
        hi[i] = make_uint2(h0, h1);
        lo[i] = make_uint2(l0, l1);
    }
}

// ---------------------------------------------------------------------------
// GEMM (NT) on pre-split bf16: C = (Ah+Al) @ (Wh+Wl)^T + bias [3-term]
// Output: fp32 C (+res) if Ch==null, else split bf16 (Ch, Cl).
// sm_103a: cp.async 3-stage pipeline feeding tcgen05 SS MMA.
// ---------------------------------------------------------------------------
#define GK_CHUNK 64
#define GTILE 16384                      // one 128x64 bf16 tile
#define GSTAGE (4 * GTILE)               // Ah,Al,Wh,Wl = 64KB
#define GEMM_SMEM (1024 + 3 * GSTAGE)    // 197632

#define GEMM_IDESC ((1u << 4) | (1u << 7) | (1u << 10) | ((128u / 8) << 17) | ((128u / 16) << 24))
#define PV_IDESC   ((1u << 4) | (1u << 7) | (1u << 10) | ((64u / 8) << 17) | ((128u / 16) << 24))

__global__ __launch_bounds__(256, 1)
void gemm_tc(const __nv_bfloat16* __restrict__ Ah, const __nv_bfloat16* __restrict__ Al,
             const __nv_bfloat16* __restrict__ Wh, const __nv_bfloat16* __restrict__ Wl,
             const float* __restrict__ bias, const float* __restrict__ res,
             float* __restrict__ C,
             __nv_bfloat16* __restrict__ Ch, __nv_bfloat16* __restrict__ Cl,
             int M, int N, int K)
{
    extern __shared__ char smem[];
    const int tid  = threadIdx.x;
    const int wid  = tid >> 5;
    const int lane = tid & 31;
    const int m0 = blockIdx.y * 128;
    const int n0 = blockIdx.x * 128;
#if HAS_TCGEN05
    const uint32_t smem_base = smem_u32(smem);
    const uint32_t mb[3] = { smem_base + 8, smem_base + 16, smem_base + 24 };

    if (wid == 0) tmem_alloc(smem_base, 128);
    if (tid == 0) { mbar_init(mb[0], 1); mbar_init(mb[1], 1); mbar_init(mb[2], 1); }
    __syncthreads();
    uint32_t tmem;
    asm volatile("ld.shared.b32 %0, [%1];" : "=r"(tmem) : "r"(smem_base));

    const int nch = K / GK_CHUNK;   // 16
    uint32_t ph[3] = {0, 0, 0};

    auto issue_chunk = [&](int p) {
        const uint32_t sbase = smem_base + 1024 + (uint32_t)(p % 3) * GSTAGE;
        const int k0 = p * GK_CHUNK;
        #pragma unroll
        for (int it = 0; it < 4; it++) {
            const int idx = tid + it * 256;
            const int r = idx >> 3, g = idx & 7;
            const uint32_t so = SWZ((uint32_t)(r * 128 + g * 16));
            const size_t ao = ((size_t)(m0 + r) * K + k0) * 2 + g * 16;
            const size_t wo = ((size_t)(n0 + r) * K + k0) * 2 + g * 16;
            cp_async16(sbase + so,             (const char*)Ah + ao);
            cp_async16(sbase + GTILE + so,     (const char*)Al + ao);
            cp_async16(sbase + 2 * GTILE + so, (const char*)Wh + wo);
            cp_async16(sbase + 3 * GTILE + so, (const char*)Wl + wo);
        }
        cp_commit();
    };

    // prologue: chunks 0, 1 in flight
    issue_chunk(0);
    issue_chunk(1);

    for (int n = 0; n < nch; n++) {
        const int p = n + 2;
        if (p < nch) {
            const int pb = p % 3;
            if (p >= 3) { mbar_wait(mb[pb], ph[pb]); ph[pb] ^= 1; }  // MMA of p-3 done
            issue_chunk(p);
            cp_wait<2>();
        } else if (p == nch) {
            cp_wait<1>();
        } else {
            cp_wait<0>();
        }
        __syncthreads();

        if (wid == 0) {
            fence_async_smem();
            if (elect_one_pred()) {
                const uint32_t tb = smem_base + 1024 + (uint32_t)(n % 3) * GSTAGE;
                const uint64_t dAh = make_desc(tb);
                const uint64_t dAl = make_desc(tb + GTILE);
                const uint64_t dWh = make_desc(tb + 2 * GTILE);
                const uint64_t dWl = make_desc(tb + 3 * GTILE);
                #pragma unroll
                for (int ks = 0; ks < 4; ks++)
                    mma_bf16_ss(tmem, dAh + ks * 2, dWh + ks * 2, GEMM_IDESC,
                                (n != 0) || (ks != 0));
                #pragma unroll
                for (int ks = 0; ks < 4; ks++)
                    mma_bf16_ss(tmem, dAh + ks * 2, dWl + ks * 2, GEMM_IDESC, 1);
                #pragma unroll
                for (int ks = 0; ks < 4; ks++)
                    mma_bf16_ss(tmem, dAl + ks * 2, dWh + ks * 2, GEMM_IDESC, 1);
                mma_commit(mb[n % 3]);
            }
        }
    }

    // drain all three buffers' last commits
    mbar_wait(mb[0], ph[0]);
    mbar_wait(mb[1], ph[1]);
    mbar_wait(mb[2], ph[2]);
    tc_fence_after();

    // epilogue
    {
        const int sub   = wid & 3;
        const int cbase = (wid >> 2) * 64;
        uint32_t d[64];
        TCGEN05_LD_X32(d, tmem + cbase);
        TCGEN05_LD_X32(d + 32, tmem + cbase + 32);
        tmem_wait_ld();
        tc_fence_before();

        const int row = m0 + sub * 32 + lane;
        const size_t cb = (size_t)row * N + n0 + cbase;
        const float* brow = bias + n0 + cbase;
        if (Ch) {
            uint2* hrow = (uint2*)(Ch + cb);
            uint2* lrow = (uint2*)(Cl + cb);
            #pragma unroll
            for (int j = 0; j < 64; j += 4) {
                float4 bb = *(const float4*)(brow + j);
                float o0 = __uint_as_float(d[j + 0]) + bb.x;
                float o1 = __uint_as_float(d[j + 1]) + bb.y;
                float o2 = __uint_as_float(d[j + 2]) + bb.z;
                float o3 = __uint_as_float(d[j + 3]) + bb.w;
                uint32_t h0, l0, h1, l1;
                split2(o0, o1, h0, l0);
                split2(o2, o3, h1, l1);
                hrow[j >> 2] = make_uint2(h0, h1);
                lrow[j >> 2] = make_uint2(l0, l1);
            }
        } else {
            float* crow = C + cb;
            const float* rrow = res ? (res + cb) : nullptr;
            #pragma unroll
            for (int j = 0; j < 64; j += 4) {
                float4 bb = *(const float4*)(brow + j);
                float4 o;
                o.x = __uint_as_float(d[j + 0]) + bb.x;
                o.y = __uint_as_float(d[j + 1]) + bb.y;
                o.z = __uint_as_float(d[j + 2]) + bb.z;
                o.w = __uint_as_float(d[j + 3]) + bb.w;
                if (rrow) {
                    float4 rr = *(const float4*)(rrow + j);
                    o.x += rr.x; o.y += rr.y; o.z += rr.z; o.w += rr.w;
                }
                *(float4*)(crow + j) = o;
            }
        }
    }

    __syncthreads();
    if (wid == 0) {
        tmem_relinquish();
        tmem_dealloc(tmem, 128);
    }
#else
    // ---- FFMA fallback (never expected to run; correctness insurance) ----
    float* As = (float*)smem;
    float* Ws = (float*)smem + 8 * 128;

    const int tx = tid & 15;
    const int ty = tid >> 4;
    const int lr = tid >> 1;
    const int lk = (tid & 1) * 4;

    float acc[8][8] = {};

    for (int k0 = 0; k0 < K; k0 += 8) {
        #pragma unroll
        for (int j = 0; j < 4; j++) {
            const size_t ai = (size_t)(m0 + lr) * K + k0 + lk + j;
            const size_t wi = (size_t)(n0 + lr) * K + k0 + lk + j;
            As[(lk + j) * 128 + lr] = __bfloat162float(Ah[ai]) + __bfloat162float(Al[ai]);
            Ws[(lk + j) * 128 + lr] = __bfloat162float(Wh[wi]) + __bfloat162float(Wl[wi]);
        }
        __syncthreads();
        #pragma unroll
        for (int k = 0; k < 8; k++) {
            float ra[8], rw[8];
            #pragma unroll
            for (int i = 0; i < 8; i++) ra[i] = As[k * 128 + ty * 8 + i];
            #pragma unroll
            for (int i = 0; i < 8; i++) rw[i] = Ws[k * 128 + tx * 8 + i];
            #pragma unroll
            for (int i = 0; i < 8; i++)
                #pragma unroll
                for (int j = 0; j < 8; j++)
                    acc[i][j] = fmaf(ra[i], rw[j], acc[i][j]);
        }
        __syncthreads();
    }

    #pragma unroll
    for (int i = 0; i < 8; i++) {
        const int m = m0 + ty * 8 + i;
        #pragma unroll
        for (int j = 0; j < 8; j += 2) {
            const int n = n0 + tx * 8 + j;
            float c0 = acc[i][j]     + bias[n];
            float c1 = acc[i][j + 1] + bias[n + 1];
            const size_t ci = (size_t)m * N + n;
            if (Ch) {
                uint32_t h0, l0;
                split2(c0, c1, h0, l0);
                *(uint32_t*)(Ch + ci) = h0;
                *(uint32_t*)(Cl + ci) = l0;
            } else {
                if (res) { c0 += res[ci]; c1 += res[ci + 1]; }
                C[ci] = c0; C[ci + 1] = c1;
            }
        }
    }
#endif
}

// ---------------------------------------------------------------------------
// Flash attention on pre-split bf16 Q/K/V; writes split bf16 attn.
// Grid (LQ/128, H, B), 256 threads.
// ---------------------------------------------------------------------------
#define FL_S0   0
#define FL_O0   128
#define FL_PHI  192
#define FL_PLO  256
#define FL_TCOLS 512
#define FLQ_HI  1024
#define FLQ_LO  (FLQ_HI + 16384)
#define FLK_HI  (FLQ_LO + 16384)
#define FLK_LO  (FLK_HI + 16384)
#define FLV_HI  (FLK_LO + 16384)
#define FLV_LO  (FLV_HI + 16384)
#define FLMASK  (FLV_LO + 16384)     // 128 ints
#define FLBUF   (FLMASK + 512)       // 2 x 256 floats
#define FLASH_SMEM (FLBUF + 2048 + 64)

__global__ __launch_bounds__(256, 1) void flash_kernel(
    const __nv_bfloat16* __restrict__ Qh, const __nv_bfloat16* __restrict__ Ql,
    const __nv_bfloat16* __restrict__ KVh, const __nv_bfloat16* __restrict__ KVl,
    const int* __restrict__ mask,
    __nv_bfloat16* __restrict__ Oh, __nv_bfloat16* __restrict__ Ol)
{
    extern __shared__ char smem[];
    const int tid  = threadIdx.x;
    const int q0 = blockIdx.x * 128;
    const int h  = blockIdx.y;
    const int b  = blockIdx.z;
#if HAS_TCGEN05
    const int wid  = tid >> 5;
    const int lane = tid & 31;
    const int half = wid >> 2;
    const int sub  = wid & 3;
    const int r    = sub * 32 + lane;
    const int cbase = half * 64;
    const int dbase = half * 32;

    const uint32_t sb = smem_u32(smem);
    const uint32_t mbS = sb + 8, mbP = sb + 16;

    if (wid == 0) tmem_alloc(sb, FL_TCOLS);
    if (tid == 0) { mbar_init(mbS, 1); mbar_init(mbP, 1); }
    __syncthreads();
    uint32_t tmem;
    asm volatile("ld.shared.b32 %0, [%1];" : "=r"(tmem) : "r"(sb));

    const int* mg = mask + (size_t)b * LKV;
    float* sbufA = (float*)(smem + FLBUF);
    float* sbufB = sbufA + 256;
    int* smask = (int*)(smem + FLMASK);

    // Q tile copy (once)
    {
        #pragma unroll
        for (int it = 0; it < 4; it++) {
            const int idx = tid + it * 256;
            const int rq = idx >> 3, g = idx & 7;
            const uint32_t so = SWZ((uint32_t)(rq * 128 + g * 16));
            const size_t gb = ((size_t)(b * LQ + q0 + rq) * D + h * HD) * 2 + g * 16;
            cp_async16(sb + FLQ_HI + so, (const char*)Qh + gb);
            cp_async16(sb + FLQ_LO + so, (const char*)Ql + gb);
        }
        cp_commit();
    }

    auto issueK = [&](int kvb) {
        #pragma unroll
        for (int it = 0; it < 4; it++) {
            const int idx = tid + it * 256;
            const int rk = idx >> 3, g = idx & 7;
            const uint32_t so = SWZ((uint32_t)(rk * 128 + g * 16));
            const size_t gb = ((size_t)(b * LKV + kvb + rk) * (2 * D) + h * HD) * 2 + g * 16;
            cp_async16(sb + FLK_HI + so, (const char*)KVh + gb);
            cp_async16(sb + FLK_LO + so, (const char*)KVl + gb);
        }
        cp_commit();
    };

    issueK(0);   // lengths >= 512, so block 0 is always valid

    float m_run = -3e38f, l_run = 0.f;
    float Oreg[32];
    #pragma unroll
    for (int j = 0; j < 32; j++) Oreg[j] = 0.f;

    uint32_t sph = 0, pph = 0;
    const uint64_t dQh = make_desc(sb + FLQ_HI);
    const uint64_t dQl = make_desc(sb + FLQ_LO);
    const uint64_t dKh = make_desc(sb + FLK_HI);
    const uint64_t dKl = make_desc(sb + FLK_LO);
    const uint64_t dVh = make_desc(sb + FLV_HI);
    const uint64_t dVl = make_desc(sb + FLV_LO);

    int kv0 = 0;
    while (true) {
        // a: all outstanding copies (Q + K(n)) done
        cp_wait<0>();
        if (tid < 128) smask[tid] = mg[kv0 + tid];
        __syncthreads();

        // b: S = Q @ K^T
        if (wid == 0) {
            fence_async_smem();
            if (elect_one_pred()) {
                #pragma unroll
                for (int k = 0; k < 4; k++)
                    mma_bf16_ss(tmem + FL_S0, dQh + k * 2, dKh + k * 2, GEMM_IDESC, k != 0);
                #pragma unroll
                for (int k = 0; k < 4; k++)
                    mma_bf16_ss(tmem + FL_S0, dQh + k * 2, dKl + k * 2, GEMM_IDESC, 1);
                #pragma unroll
                for (int k = 0; k < 4; k++)
                    mma_bf16_ss(tmem + FL_S0, dQl + k * 2, dKh + k * 2, GEMM_IDESC, 1);
                mma_commit(mbS);
            }
        }

        // c: V^T transpose copy (bf16, blocked atoms) — overlaps S MMA
        #pragma unroll
        for (int it = 0; it < 8; it++) {
            const int idx = tid + it * 256;
            const int c  = idx >> 4;
            const int d0 = (idx & 15) * 4;
            const size_t ge = (size_t)(b * LKV + kv0 + c) * (2 * D) + D + h * HD + d0;
            uint2 vh = *(const uint2*)(KVh + ge);
            uint2 vl = *(const uint2*)(KVl + ge);
            const __nv_bfloat16* ph4 = (const __nv_bfloat16*)&vh;
            const __nv_bfloat16* pl4 = (const __nv_bfloat16*)&vl;
            #pragma unroll
            for (int j = 0; j < 4; j++) {
                const int row = d0 + j;
                const uint32_t off = (uint32_t)(((row >> 3) + (c >> 6) * 8) * 1024
                                               + (row & 7) * 128 + (c & 63) * 2);
                const uint32_t so = SWZ(off);
                *(__nv_bfloat16*)(smem + FLV_HI + so) = ph4[j];
                *(__nv_bfloat16*)(smem + FLV_LO + so) = pl4[j];
            }
        }

        // d: wait S, read, softmax
        mbar_wait(mbS, sph); sph ^= 1;
        tc_fence_after();
        float sv[64];
        TCGEN05_LD_X32((uint32_t*)sv,        tmem + FL_S0 + cbase);
        TCGEN05_LD_X32(((uint32_t*)sv) + 32, tmem + FL_S0 + cbase + 32);
        tmem_wait_ld();

        float mx = -3e38f;
        #pragma unroll
        for (int j = 0; j < 64; j++) {
            const float x = (smask[cbase + j] != 0) ? NEGV : sv[j] * ATTN_SCALE;
            sv[j] = x;
            mx = fmaxf(mx, x);
        }
        sbufA[half * 128 + r] = mx;
        __syncthreads();
        const float m_new = fmaxf(m_run, fmaxf(mx, sbufA[(1 - half) * 128 + r]));
        float sum = 0.f;
        #pragma unroll
        for (int j = 0; j < 64; j++) {
            const float p = __expf(sv[j] - m_new);
            sv[j] = p;
            sum += p;
        }
        sbufB[half * 128 + r] = sum;
        __syncthreads();
        sum += sbufB[(1 - half) * 128 + r];
        const float alpha = __expf(m_run - m_new);
        l_run = l_run * alpha + sum;
        m_run = m_new;

        // pack P hi/lo -> TMEM
        {
            uint32_t phi[32], plo[32];
            #pragma unroll
            for (int j = 0; j < 32; j++)
                split2(sv[2 * j], sv[2 * j + 1], phi[j], plo[j]);
            const uint32_t wo = ((uint32_t)sub) << 21;
            TCGEN05_ST_X32(tmem + FL_PHI + half * 32 + wo, phi);
            TCGEN05_ST_X32(tmem + FL_PLO + half * 32 + wo, plo);
            tmem_wait_st();
        }
        tc_fence_before();
        __syncthreads();

        const bool nextv = (kv0 + 128 < LKV) && (mg[kv0 + 128] == 0);

        // e: PV MMA (P in TMEM, V^T in smem)
        if (wid == 0) {
            fence_async_smem();
            if (elect_one_pred()) {
                tc_fence_after();
                #pragma unroll
                for (int k = 0; k < 8; k++) {
                    const uint64_t vo = (k < 4) ? (uint64_t)(k * 2)
                                               : (uint64_t)(512 + (k - 4) * 2);
                    mma_bf16_ts(tmem + FL_O0, tmem + FL_PHI + k * 8,
                                dVh + vo, PV_IDESC, k != 0);
                }
                #pragma unroll
                for (int k = 0; k < 8; k++) {
                    const uint64_t vo = (k < 4) ? (uint64_t)(k * 2)
                                               : (uint64_t)(512 + (k - 4) * 2);
                    mma_bf16_ts(tmem + FL_O0, tmem + FL_PHI + k * 8,
                                dVl + vo, PV_IDESC, 1);
                }
                #pragma unroll
                for (int k = 0; k < 8; k++) {
                    const uint64_t vo = (k < 4) ? (uint64_t)(k * 2)
                                               : (uint64_t)(512 + (k - 4) * 2);
                    mma_bf16_ts(tmem + FL_O0, tmem + FL_PLO + k * 8,
                                dVh + vo, PV_IDESC, 1);
                }
                mma_commit(mbP);
            }
        }

        // f: prefetch next K under PV (S MMA already done -> FLK reusable)
        if (nextv) issueK(kv0 + 128);

        // g: wait PV, merge into registers
        mbar_wait(mbP, pph); pph ^= 1;
        tc_fence_after();
        {
            uint32_t pv[32];
            TCGEN05_LD_X32(pv, tmem + FL_O0 + dbase);
            tmem_wait_ld();
            #pragma unroll
            for (int j = 0; j < 32; j++)
                Oreg[j] = Oreg[j] * alpha + __uint_as_float(pv[j]);
        }
        __syncthreads();

        if (!nextv) break;
        kv0 += 128;
    }

    // epilogue: split bf16 output
    {
        const float inv = 1.f / l_run;
        const size_t ob = (size_t)(b * LQ + q0 + r) * D + h * HD + dbase;
        uint2* hrow = (uint2*)(Oh + ob);
        uint2* lrow = (uint2*)(Ol + ob);
        #pragma unroll
        for (int j = 0; j < 32; j += 4) {
            uint32_t h0, l0, h1, l1;
            split2(Oreg[j] * inv, Oreg[j + 1] * inv, h0, l0);
            split2(Oreg[j + 2] * inv, Oreg[j + 3] * inv, h1, l1);
            hrow[j >> 2] = make_uint2(h0, h1);
            lrow[j >> 2] = make_uint2(l0, l1);
        }
    }
    __syncthreads();
    if (wid == 0) {
        tmem_relinquish();
        tmem_dealloc(tmem, FL_TCOLS);
    }
#else
    // ---- FFMA fallback: two 64-row halves, reconstruct hi+lo ----
    float* sm  = (float*)smem;
    float* Qt  = sm;
    float* Kt  = Qt + 4096;
    float* Vs  = Kt + 4096;
    float* St  = Vs + 4096;
    float* rm  = St + 4096;
    float* rl  = rm + 64;
    float* rsc = rl + 64;

    const int tr = tid >> 4;
    const int tc = tid & 15;
    const int r0 = tr * 4;
    const int c0 = tc * 4;

    for (int qh = 0; qh < 2; qh++) {
        const int qq0 = q0 + qh * 64;
        __syncthreads();

        for (int i = tid; i < 64 * 64; i += 256) {
            const int rr = i >> 6, kq = i & 63;
            const size_t gi = (size_t)(b * LQ + qq0 + rr) * D + h * HD + kq;
            Qt[kq * 64 + rr] = __bfloat162float(Qh[gi]) + __bfloat162float(Ql[gi]);
        }
        if (tid < 64) { rm[tid] = -3e38f; rl[tid] = 0.f; }
        float acc[4][4] = {};
        __syncthreads();

        const int* mg = mask + (size_t)b * LKV;

        for (int kv0 = 0; kv0 < LKV; kv0 += 64) {
            if (mg[kv0] != 0) break;

            for (int i = tid; i < 64 * 64; i += 256) {
                const int c = i >> 6, kq = i & 63;
                const size_t gk = (size_t)(b * LKV + kv0 + c) * (2 * D) + h * HD + kq;
                const size_t gv = gk + D;
                Kt[kq * 64 + c] = __bfloat162float(KVh[gk]) + __bfloat162float(KVl[gk]);
                Vs[c * 64 + kq] = __bfloat162float(KVh[gv]) + __bfloat162float(KVl[gv]);
            }
            __syncthreads();

            float s[4][4] = {};
            #pragma unroll
            for (int k = 0; k < 64; k++) {
                float rq[4], rk[4];
                #pragma unroll
                for (int i = 0; i < 4; i++) rq[i] = Qt[k * 64 + r0 + i];
                #pragma unroll
                for (int j = 0; j < 4; j++) rk[j] = Kt[k * 64 + c0 + j];
                #pragma unroll
                for (int i = 0; i < 4; i++)
                    #pragma unroll
                    for (int j = 0; j < 4; j++)
                        s[i][j] = fmaf(rq[i], rk[j], s[i][j]);
            }
            #pragma unroll
            for (int j = 0; j < 4; j++) {
                const bool msk = (mg[kv0 + c0 + j] != 0);
                #pragma unroll
                for (int i = 0; i < 4; i++)
                    St[(c0 + j) * 64 + r0 + i] = msk ? NEGV : s[i][j] * ATTN_SCALE;
            }
            __syncthreads();

            if (tid < 64) {
                const int rr = tid;
                const float mold = rm[rr];
                float mxx = mold;
                for (int c = 0; c < 64; c++) mxx = fmaxf(mxx, St[c * 64 + rr]);
                float sum = 0.f;
                for (int c = 0; c < 64; c++) {
                    float p = __expf(St[c * 64 + rr] - mxx);
                    sum += p;
                    St[c * 64 + rr] = p;
                }
                const float scale = __expf(mold - mxx);
                rl[rr] = rl[rr] * scale + sum;
                rm[rr] = mxx;
                rsc[rr] = scale;
            }
            __syncthreads();

            float sci[4];
            #pragma unroll
            for (int i = 0; i < 4; i++) sci[i] = rsc[r0 + i];
            #pragma unroll
            for (int i = 0; i < 4; i++)
                #pragma unroll
                for (int j = 0; j < 4; j++)
                    acc[i][j] *= sci[i];

            #pragma unroll
            for (int c = 0; c < 64; c++) {
                float rp[4], rv[4];
                #pragma unroll
                for (int i = 0; i < 4; i++) rp[i] = St[c * 64 + r0 + i];
                #pragma unroll
                for (int j = 0; j < 4; j++) rv[j] = Vs[c * 64 + c0 + j];
                #pragma unroll
                for (int i = 0; i < 4; i++)
                    #pragma unroll
                    for (int j = 0; j < 4; j++)
                        acc[i][j] = fmaf(rp[i], rv[j], acc[i][j]);
            }
            __syncthreads();
        }

        float invl[4];
        #pragma unroll
        for (int i = 0; i < 4; i++) invl[i] = 1.f / rl[r0 + i];
        #pragma unroll
        for (int i = 0; i < 4; i++) {
            const size_t ob = (size_t)(b * LQ + qq0 + r0 + i) * D + h * HD + c0;
            #pragma unroll
            for (int j = 0; j < 4; j += 2) {
                uint32_t hh, ll;
                split2(acc[i][j] * invl[i], acc[i][j + 1] * invl[i], hh, ll);
                *(uint32_t*)(Oh + ob + j) = hh;
                *(uint32_t*)(Ol + ob + j) = ll;
            }
        }
    }
#endif
}

// ---------------------------------------------------------------------------
// Launch
// ---------------------------------------------------------------------------
extern "C" void kernel_launch(void* const* d_in, const int* in_sizes, int n_in,
                              void* d_out, int out_size)
{
    const float* q       = (const float*)d_in[0];
    const float* kv      = (const float*)d_in[1];
    const int*   mask    = (const int*)d_in[2];
    const float* nqw     = (const float*)d_in[3];
    const float* nqb     = (const float*)d_in[4];
    const float* nkw     = (const float*)d_in[5];
    const float* nkb     = (const float*)d_in[6];
    const float* Wq      = (const float*)d_in[7];
    const float* bq      = (const float*)d_in[8];
    const float* Wkv     = (const float*)d_in[9];
    const float* bkv     = (const float*)d_in[10];
    const float* Wo      = (const float*)d_in[11];
    const float* bo      = (const float*)d_in[12];
    float* out = (float*)d_out;

    __nv_bfloat16 *qn_h, *qn_l, *kvn_h, *kvn_l, *wq_h, *wq_l, *wkv_h, *wkv_l;
    __nv_bfloat16 *wo_h, *wo_l, *qh_h, *qh_l, *kvp_h, *kvp_l, *at_h, *at_l;
    cudaGetSymbolAddress((void**)&qn_h,  g_qn_hi);
    cudaGetSymbolAddress((void**)&qn_l,  g_qn_lo);
    cudaGetSymbolAddress((void**)&kvn_h, g_kvn_hi);
    cudaGetSymbolAddress((void**)&kvn_l, g_kvn_lo);
    cudaGetSymbolAddress((void**)&wq_h,  g_wq_hi);
    cudaGetSymbolAddress((void**)&wq_l,  g_wq_lo);
    cudaGetSymbolAddress((void**)&wkv_h, g_wkv_hi);
    cudaGetSymbolAddress((void**)&wkv_l, g_wkv_lo);
    cudaGetSymbolAddress((void**)&wo_h,  g_wo_hi);
    cudaGetSymbolAddress((void**)&wo_l,  g_wo_lo);
    cudaGetSymbolAddress((void**)&qh_h,  g_qh_hi);
    cudaGetSymbolAddress((void**)&qh_l,  g_qh_lo);
    cudaGetSymbolAddress((void**)&kvp_h, g_kvp_hi);
    cudaGetSymbolAddress((void**)&kvp_l, g_kvp_lo);
    cudaGetSymbolAddress((void**)&at_h,  g_attn_hi);
    cudaGetSymbolAddress((void**)&at_l,  g_attn_lo);

    static int attr_set = 0;
    if (!attr_set) {
        cudaFuncSetAttribute(gemm_tc,
                             cudaFuncAttributeMaxDynamicSharedMemorySize, GEMM_SMEM);
        cudaFuncSetAttribute(flash_kernel,
                             cudaFuncAttributeMaxDynamicSharedMemorySize, FLASH_SMEM);
        attr_set = 1;
    }

    // 1. LayerNorms -> split bf16
    ln_split_kernel<<<B * LQ, 256>>>(q, nqw, nqb, qn_h, qn_l);
    ln_split_kernel<<<B * LKV, 256>>>(kv, nkw, nkb, kvn_h, kvn_l);

    // 2. Weight splits
    split_kernel<<<(D * D / 4 + 255) / 256, 256>>>(
        (const float4*)Wq, (uint2*)wq_h, (uint2*)wq_l, D * D / 4);
    split_kernel<<<(2 * D * D / 4 + 255) / 256, 256>>>(
        (const float4*)Wkv, (uint2*)wkv_h, (uint2*)wkv_l, 2 * D * D / 4);
    split_kernel<<<(D * D / 4 + 255) / 256, 256>>>(
        (const float4*)Wo, (uint2*)wo_h, (uint2*)wo_l, D * D / 4);

    // 3. Projections (split-bf16 in, split-bf16 out)
    {
        dim3 grid(D / 128, (B * LQ) / 128);
        gemm_tc<<<grid, 256, GEMM_SMEM>>>(qn_h, qn_l, wq_h, wq_l, bq,
                                          nullptr, nullptr, qh_h, qh_l,
                                          B * LQ, D, D);
    }
    {
        dim3 grid((2 * D) / 128, (B * LKV) / 128);
        gemm_tc<<<grid, 256, GEMM_SMEM>>>(kvn_h, kvn_l, wkv_h, wkv_l, bkv,
                                          nullptr, nullptr, kvp_h, kvp_l,
                                          B * LKV, 2 * D, D);
    }

    // 4. Flash attention -> split bf16 attn
    {
        dim3 grid(LQ / 128, H, B);
        flash_kernel<<<grid, 256, FLASH_SMEM>>>(qh_h, qh_l, kvp_h, kvp_l,
                                                mask, at_h, at_l);
    }

    // 5. Output projection + residual (fp32 out)
    {
        dim3 grid(D / 128, (B * LQ) / 128);
        gemm_tc<<<grid, 256, GEMM_SMEM>>>(at_h, at_l, wo_h, wo_l, bo,
                                          q, out, nullptr, nullptr,
                                          B * LQ, D, D);
    }
}